// round 9
// baseline (speedup 1.0000x reference)
#include <cuda_runtime.h>
#include <cuda_bf16.h>
#include <math.h>
#include <stdint.h>

// Problem constants
#define S_LEN   4096
#define HIDDEN  2304
#define NH      8
#define NKV     4
#define HD      256
#define QKVN    4096
#define SWIN    2048
#define SCALE_F 0.0625f
#define CAP_F   50.0f

// Scratch (device globals)
__device__ float g_qkv[(size_t)S_LEN * QKVN];
__device__ float g_ao[(size_t)S_LEN * (NH * HD)];
// Pre-split K/V (bf16 hi/lo), laid out exactly as the mma fragments want:
//   gK*: [kvh][key 4096][dim-pair 128 u32]   (row-major keys, packed dim pairs)
//   gV*: [kvh][dim 256][key-pair 2048 u32]   (transposed, packed key pairs)
__device__ uint32_t gKh[(size_t)NKV * S_LEN * 128];
__device__ uint32_t gKl[(size_t)NKV * S_LEN * 128];
__device__ uint32_t gVh[(size_t)NKV * HD * (S_LEN / 2)];
__device__ uint32_t gVl[(size_t)NKV * HD * (S_LEN / 2)];

// ---------------------------------------------------------------------------
// Shared helpers: verified m16n8k16 bf16 mma + hi/lo split
// ---------------------------------------------------------------------------
__device__ __forceinline__ void mma_bf16(float* d,
    uint32_t a0, uint32_t a1, uint32_t a2, uint32_t a3, uint32_t b0, uint32_t b1)
{
    asm volatile(
        "mma.sync.aligned.m16n8k16.row.col.f32.bf16.bf16.f32 "
        "{%0,%1,%2,%3}, {%4,%5,%6,%7}, {%8,%9}, {%0,%1,%2,%3};\n"
        : "+f"(d[0]), "+f"(d[1]), "+f"(d[2]), "+f"(d[3])
        : "r"(a0), "r"(a1), "r"(a2), "r"(a3), "r"(b0), "r"(b1));
}

__device__ __forceinline__ void split2(float x, float y, uint32_t& hi, uint32_t& lo)
{
    __nv_bfloat16 hx = __float2bfloat16_rn(x);
    __nv_bfloat16 hy = __float2bfloat16_rn(y);
    __nv_bfloat16 lx = __float2bfloat16_rn(x - __bfloat162float(hx));
    __nv_bfloat16 ly = __float2bfloat16_rn(y - __bfloat162float(hy));
    __nv_bfloat162 h2 = __halves2bfloat162(hx, hy);
    __nv_bfloat162 l2 = __halves2bfloat162(lx, ly);
    hi = *(uint32_t*)&h2;
    lo = *(uint32_t*)&l2;
}

// ---------------------------------------------------------------------------
// bf16 hi/lo split GEMM (R6/R7-proven): C[m, coff+n] = sum_k A[m,k]*B[n,k]
// ---------------------------------------------------------------------------
#define BSTR 12
#define BBUF (128 * BSTR)

__global__ void __launch_bounds__(256) gemm_bf16s(
    const float* __restrict__ A, const float* __restrict__ B, float* __restrict__ C,
    int K, int lda, int ldb, int ldc, int coff)
{
    __shared__ uint32_t Ah[2][BBUF], Al[2][BBUF];
    __shared__ uint32_t Bh[2][BBUF], Bl[2][BBUF];

    const int tid  = threadIdx.x;
    const int warp = tid >> 5, lane = tid & 31;
    const int g    = lane >> 2, c4 = lane & 3;
    const int wm   = (warp >> 1) * 32, wn = (warp & 1) * 64;
    const int bm   = blockIdx.y * 128, bn = blockIdx.x * 128;

    const int lrow = tid >> 1;
    const int lh   = (tid & 1) * 4;

    const float* Abase = A + (size_t)(bm + lrow) * lda + lh * 2;
    const float* Bbase = B + (size_t)(bn + lrow) * ldb + lh * 2;

    float acc[2][8][4];
#pragma unroll
    for (int i = 0; i < 2; i++)
#pragma unroll
        for (int j = 0; j < 8; j++)
#pragma unroll
            for (int t = 0; t < 4; t++) acc[i][j][t] = 0.f;

    const int nc = K >> 4;
    float4 ra0, ra1, rb0, rb1;

    ra0 = *(const float4*)(Abase);
    ra1 = *(const float4*)(Abase + 4);
    rb0 = *(const float4*)(Bbase);
    rb1 = *(const float4*)(Bbase + 4);
    {
        uint4 uh, ul;
        split2(ra0.x, ra0.y, uh.x, ul.x); split2(ra0.z, ra0.w, uh.y, ul.y);
        split2(ra1.x, ra1.y, uh.z, ul.z); split2(ra1.z, ra1.w, uh.w, ul.w);
        *(uint4*)&Ah[0][lrow * BSTR + lh] = uh;
        *(uint4*)&Al[0][lrow * BSTR + lh] = ul;
        split2(rb0.x, rb0.y, uh.x, ul.x); split2(rb0.z, rb0.w, uh.y, ul.y);
        split2(rb1.x, rb1.y, uh.z, ul.z); split2(rb1.z, rb1.w, uh.w, ul.w);
        *(uint4*)&Bh[0][lrow * BSTR + lh] = uh;
        *(uint4*)&Bl[0][lrow * BSTR + lh] = ul;
    }
    __syncthreads();

    for (int ch = 0; ch < nc; ch++) {
        const int p = ch & 1;
        if (ch + 1 < nc) {
            const float* ap = Abase + (size_t)(ch + 1) * 16;
            const float* bp = Bbase + (size_t)(ch + 1) * 16;
            ra0 = *(const float4*)(ap);
            ra1 = *(const float4*)(ap + 4);
            rb0 = *(const float4*)(bp);
            rb1 = *(const float4*)(bp + 4);
        }

        uint32_t ah[2][4], al[2][4];
#pragma unroll
        for (int i = 0; i < 2; i++) {
            const int r = wm + i * 16 + g;
            ah[i][0] = Ah[p][r * BSTR + c4];       ah[i][1] = Ah[p][(r + 8) * BSTR + c4];
            ah[i][2] = Ah[p][r * BSTR + c4 + 4];   ah[i][3] = Ah[p][(r + 8) * BSTR + c4 + 4];
            al[i][0] = Al[p][r * BSTR + c4];       al[i][1] = Al[p][(r + 8) * BSTR + c4];
            al[i][2] = Al[p][r * BSTR + c4 + 4];   al[i][3] = Al[p][(r + 8) * BSTR + c4 + 4];
        }
#pragma unroll
        for (int j = 0; j < 8; j++) {
            const int n = wn + j * 8 + g;
            uint32_t bh0 = Bh[p][n * BSTR + c4], bh1 = Bh[p][n * BSTR + c4 + 4];
            uint32_t bl0 = Bl[p][n * BSTR + c4], bl1 = Bl[p][n * BSTR + c4 + 4];
#pragma unroll
            for (int i = 0; i < 2; i++) {
                mma_bf16(acc[i][j], ah[i][0], ah[i][1], ah[i][2], ah[i][3], bh0, bh1);
                mma_bf16(acc[i][j], ah[i][0], ah[i][1], ah[i][2], ah[i][3], bl0, bl1);
                mma_bf16(acc[i][j], al[i][0], al[i][1], al[i][2], al[i][3], bh0, bh1);
            }
        }

        if (ch + 1 < nc) {
            const int q = p ^ 1;
            uint4 uh, ul;
            split2(ra0.x, ra0.y, uh.x, ul.x); split2(ra0.z, ra0.w, uh.y, ul.y);
            split2(ra1.x, ra1.y, uh.z, ul.z); split2(ra1.z, ra1.w, uh.w, ul.w);
            *(uint4*)&Ah[q][lrow * BSTR + lh] = uh;
            *(uint4*)&Al[q][lrow * BSTR + lh] = ul;
            split2(rb0.x, rb0.y, uh.x, ul.x); split2(rb0.z, rb0.w, uh.y, ul.y);
            split2(rb1.x, rb1.y, uh.z, ul.z); split2(rb1.z, rb1.w, uh.w, ul.w);
            *(uint4*)&Bh[q][lrow * BSTR + lh] = uh;
            *(uint4*)&Bl[q][lrow * BSTR + lh] = ul;
        }
        __syncthreads();
    }

#pragma unroll
    for (int i = 0; i < 2; i++) {
        const int r0 = bm + wm + i * 16 + g;
#pragma unroll
        for (int j = 0; j < 8; j++) {
            const int cc = coff + bn + wn + j * 8 + c4 * 2;
            *(float2*)(C + (size_t)r0 * ldc + cc)       = make_float2(acc[i][j][0], acc[i][j][1]);
            *(float2*)(C + (size_t)(r0 + 8) * ldc + cc) = make_float2(acc[i][j][2], acc[i][j][3]);
        }
    }
}

// ---------------------------------------------------------------------------
// RoPE (proven).
// ---------------------------------------------------------------------------
__global__ void rope_kernel(float* __restrict__ qkv, const int* __restrict__ pos_ids)
{
    const int s = blockIdx.x;
    const int d = threadIdx.x;
    const double invf = exp(-(double)d * (9.210340371976184 / 128.0));
    const double ang  = (double)pos_ids[s] * invf;
    const float c  = (float)cos(ang);
    const float si = (float)sin(ang);

    float* row = qkv + (size_t)s * QKVN;
#pragma unroll
    for (int head = 0; head < 12; head++) {
        const int base = head * 256;
        const float x0 = row[base + d];
        const float x1 = row[base + d + 128];
        row[base + d]       = x0 * c - x1 * si;
        row[base + d + 128] = x1 * c + x0 * si;
    }
}

// ---------------------------------------------------------------------------
// prep_split: one-time K/V hi/lo split into mma-fragment-ready gmem layouts.
// Runs AFTER rope (K is roped; V is not touched by rope).
// Grid (128 key-tiles, 4 kvh), block 256.
// ---------------------------------------------------------------------------
__global__ void __launch_bounds__(256) prep_split(const float* __restrict__ qkv)
{
    __shared__ unsigned short sVh[32][260], sVl[32][260];

    const int kvh = blockIdx.y;
    const int kt  = blockIdx.x * 32;
    const int tid = threadIdx.x;
    const int r   = tid >> 3;          // key row 0..31
    const int cb  = (tid & 7) * 32;    // dim block (32 floats)

    const float* krow = qkv + (size_t)(kt + r) * QKVN + NH * HD + kvh * HD + cb;
    const float* vrow = krow + NKV * HD;
    uint32_t* khp = gKh + ((size_t)kvh * S_LEN + kt + r) * 128 + cb / 2;
    uint32_t* klp = gKl + ((size_t)kvh * S_LEN + kt + r) * 128 + cb / 2;

#pragma unroll
    for (int i = 0; i < 8; i++) {
        float4 kv = *(const float4*)(krow + i * 4);
        uint32_t h0, l0, h1, l1;
        split2(kv.x, kv.y, h0, l0);
        split2(kv.z, kv.w, h1, l1);
        khp[i * 2] = h0; khp[i * 2 + 1] = h1;
        klp[i * 2] = l0; klp[i * 2 + 1] = l1;

        float4 vv = *(const float4*)(vrow + i * 4);
        uint32_t vh0, vl0, vh1, vl1;
        split2(vv.x, vv.y, vh0, vl0);
        split2(vv.z, vv.w, vh1, vl1);
        *(uint32_t*)&sVh[r][cb + i * 4]     = vh0;
        *(uint32_t*)&sVh[r][cb + i * 4 + 2] = vh1;
        *(uint32_t*)&sVl[r][cb + i * 4]     = vl0;
        *(uint32_t*)&sVl[r][cb + i * 4 + 2] = vl1;
    }
    __syncthreads();

    // transpose out: thread = dim d, write 16 u32 (32 keys packed in pairs)
    const int d = tid;
    uint32_t* vhp = gVh + ((size_t)kvh * HD + d) * (S_LEN / 2) + kt / 2;
    uint32_t* vlp = gVl + ((size_t)kvh * HD + d) * (S_LEN / 2) + kt / 2;
#pragma unroll
    for (int j = 0; j < 16; j++) {
        vhp[j] = (uint32_t)sVh[2 * j][d] | ((uint32_t)sVh[2 * j + 1][d] << 16);
        vlp[j] = (uint32_t)sVl[2 * j][d] | ((uint32_t)sVl[2 * j + 1][d] << 16);
    }
}

// ---------------------------------------------------------------------------
// Tensor-core attention v2: K and V fragments read DIRECTLY from pre-split
// gmem (L1-cached, reused across CTAs). Smem only holds Q (hi/lo) and P
// (hi/lo): 76KB -> 2 CTAs/SM. Math identical to R8 (same split values, same
// mma order) -> rel_err should reproduce exactly.
// ---------------------------------------------------------------------------
#define AQ_STR 132
#define AP_STR 20
#define QH_OFF 0
#define QL_OFF (64 * AQ_STR)
#define PH_OFF (2 * 64 * AQ_STR)
#define PL_OFF (PH_OFF + 64 * AP_STR)
#define ATTN_SMEM_U32 (PL_OFF + 64 * AP_STR)
#define ATTN_SMEM_BYTES (ATTN_SMEM_U32 * 4)

__device__ __forceinline__ float softcap_p(float s, int gq, int gk)
{
    float t = CAP_F * tanhf(s * (1.0f / CAP_F));
    bool ok = (gk <= gq) && ((gq - gk) < SWIN);
    return ok ? __expf(t - CAP_F) : 0.f;
}

__global__ void __launch_bounds__(256, 2) attn_mma2(
    const float* __restrict__ qkv, float* __restrict__ ao)
{
    extern __shared__ uint32_t smA[];
    uint32_t* Qh = smA + QH_OFF;
    uint32_t* Ql = smA + QL_OFF;
    uint32_t* Ph = smA + PH_OFF;
    uint32_t* Pl = smA + PL_OFF;
    __shared__ float LS[2][64];

    const int h   = blockIdx.y;
    const int q0  = blockIdx.x * 64;
    const int kvh = h >> 1;
    const int tid = threadIdx.x;
    const int warp = tid >> 5, lane = tid & 31;
    const int g = lane >> 2, c4 = lane & 3;
    const int wm  = (warp >> 1) * 16;   // m-group rows
    const int wh  = warp & 1;           // S: key half; PV: dim half

    // ---- Load Q tile [64 x 256], pre-scaled, split into Qh/Ql ----
    {
        const int row = tid >> 2;
        const int cb  = (tid & 3) * 64;
        const float* qrow = qkv + (size_t)(q0 + row) * QKVN + h * HD + cb;
        uint32_t* qhp = Qh + row * AQ_STR + cb / 2;
        uint32_t* qlp = Ql + row * AQ_STR + cb / 2;
#pragma unroll
        for (int i = 0; i < 16; i++) {
            float4 v = *(const float4*)(qrow + i * 4);
            v.x *= SCALE_F; v.y *= SCALE_F; v.z *= SCALE_F; v.w *= SCALE_F;
            uint32_t h0, l0, h1, l1;
            split2(v.x, v.y, h0, l0);
            split2(v.z, v.w, h1, l1);
            qhp[i * 2] = h0; qhp[i * 2 + 1] = h1;
            qlp[i * 2] = l0; qlp[i * 2 + 1] = l1;
        }
    }
    __syncthreads();

    float oacc[16][4];
#pragma unroll
    for (int nf = 0; nf < 16; nf++)
#pragma unroll
        for (int t = 0; t < 4; t++) oacc[nf][t] = 0.f;
    float lsum0 = 0.f, lsum1 = 0.f;

    int klo = q0 - (SWIN - 1);
    if (klo < 0) klo = 0;
    klo &= ~31;
    const int khi = q0 + 63;

    // base pointers for direct-gmem fragment loads
    const uint32_t* kh_b = gKh + ((size_t)kvh * S_LEN + wh * 16 + g) * 128 + c4;
    const uint32_t* kl_b = gKl + ((size_t)kvh * S_LEN + wh * 16 + g) * 128 + c4;
    const uint32_t* vh_b = gVh + ((size_t)kvh * HD + wh * 128 + g) * (S_LEN / 2) + c4;
    const uint32_t* vl_b = gVl + ((size_t)kvh * HD + wh * 128 + g) * (S_LEN / 2) + c4;

    for (int kt = klo; kt <= khi; kt += 32) {
        // ---- S = Q K^T  (K fragments straight from gKh/gKl) ----
        float sacc[2][4];
#pragma unroll
        for (int f = 0; f < 2; f++)
#pragma unroll
            for (int t = 0; t < 4; t++) sacc[f][t] = 0.f;

        const uint32_t* kh_t = kh_b + (size_t)kt * 128;
        const uint32_t* kl_t = kl_b + (size_t)kt * 128;
#pragma unroll 4
        for (int ks = 0; ks < 16; ks++) {
            const int qa = (wm + g) * AQ_STR + ks * 8 + c4;
            uint32_t ah0 = Qh[qa], ah1 = Qh[qa + 8 * AQ_STR];
            uint32_t ah2 = Qh[qa + 4], ah3 = Qh[qa + 8 * AQ_STR + 4];
            uint32_t al0 = Ql[qa], al1 = Ql[qa + 8 * AQ_STR];
            uint32_t al2 = Ql[qa + 4], al3 = Ql[qa + 8 * AQ_STR + 4];
#pragma unroll
            for (int f = 0; f < 2; f++) {
                const uint32_t* kp = kh_t + f * (8 * 128) + ks * 8;
                const uint32_t* kq = kl_t + f * (8 * 128) + ks * 8;
                uint32_t bh0 = kp[0], bh1 = kp[4];
                uint32_t bl0 = kq[0], bl1 = kq[4];
                mma_bf16(sacc[f], ah0, ah1, ah2, ah3, bh0, bh1);
                mma_bf16(sacc[f], ah0, ah1, ah2, ah3, bl0, bl1);
                mma_bf16(sacc[f], al0, al1, al2, al3, bh0, bh1);
            }
        }

        // ---- softmax + pack P (hi/lo) into smem ----
        {
            const int r0 = q0 + wm + g;
            const int kb0 = kt + wh * 16 + 2 * c4;
#pragma unroll
            for (int f = 0; f < 2; f++) {
                const int kk = kb0 + f * 8;
                float p00 = softcap_p(sacc[f][0], r0, kk);
                float p01 = softcap_p(sacc[f][1], r0, kk + 1);
                float p10 = softcap_p(sacc[f][2], r0 + 8, kk);
                float p11 = softcap_p(sacc[f][3], r0 + 8, kk + 1);
                lsum0 += p00 + p01;
                lsum1 += p10 + p11;
                uint32_t hi, lo;
                split2(p00, p01, hi, lo);
                Ph[(wm + g) * AP_STR + wh * 8 + f * 4 + c4] = hi;
                Pl[(wm + g) * AP_STR + wh * 8 + f * 4 + c4] = lo;
                split2(p10, p11, hi, lo);
                Ph[(wm + g + 8) * AP_STR + wh * 8 + f * 4 + c4] = hi;
                Pl[(wm + g + 8) * AP_STR + wh * 8 + f * 4 + c4] = lo;
            }
        }
        __syncthreads();   // P writes visible to row-group partner warp

        // ---- O += P V  (V fragments straight from gVh/gVl) ----
        const uint32_t* vh_t = vh_b + (kt >> 1);
        const uint32_t* vl_t = vl_b + (kt >> 1);
#pragma unroll
        for (int ks2 = 0; ks2 < 2; ks2++) {
            const int pa = (wm + g) * AP_STR + ks2 * 8 + c4;
            uint32_t pah0 = Ph[pa], pah1 = Ph[pa + 8 * AP_STR];
            uint32_t pah2 = Ph[pa + 4], pah3 = Ph[pa + 8 * AP_STR + 4];
            uint32_t pal0 = Pl[pa], pal1 = Pl[pa + 8 * AP_STR];
            uint32_t pal2 = Pl[pa + 4], pal3 = Pl[pa + 8 * AP_STR + 4];
#pragma unroll
            for (int nf = 0; nf < 16; nf++) {
                const uint32_t* vp = vh_t + nf * (8 * (S_LEN / 2)) + ks2 * 8;
                const uint32_t* vq = vl_t + nf * (8 * (S_LEN / 2)) + ks2 * 8;
                uint32_t vh0 = vp[0], vh1 = vp[4];
                uint32_t vl0 = vq[0], vl1 = vq[4];
                mma_bf16(oacc[nf], pah0, pah1, pah2, pah3, vh0, vh1);
                mma_bf16(oacc[nf], pah0, pah1, pah2, pah3, vl0, vl1);
                mma_bf16(oacc[nf], pal0, pal1, pal2, pal3, vh0, vh1);
            }
        }
        __syncthreads();   // PV reads done before next tile's P writes
    }

    // ---- reduce row sums across c4 lanes, then across key-half warps ----
    lsum0 += __shfl_xor_sync(0xffffffffu, lsum0, 1);
    lsum0 += __shfl_xor_sync(0xffffffffu, lsum0, 2);
    lsum1 += __shfl_xor_sync(0xffffffffu, lsum1, 1);
    lsum1 += __shfl_xor_sync(0xffffffffu, lsum1, 2);
    if (c4 == 0) {
        LS[wh][wm + g]     = lsum0;
        LS[wh][wm + g + 8] = lsum1;
    }
    __syncthreads();
    const float inv0 = 1.0f / (LS[0][wm + g] + LS[1][wm + g]);
    const float inv1 = 1.0f / (LS[0][wm + g + 8] + LS[1][wm + g + 8]);

    // ---- store O ----
    {
        float* r0p = ao + (size_t)(q0 + wm + g) * (NH * HD) + h * HD + wh * 128;
        float* r1p = ao + (size_t)(q0 + wm + g + 8) * (NH * HD) + h * HD + wh * 128;
#pragma unroll
        for (int nf = 0; nf < 16; nf++) {
            const int dc = nf * 8 + 2 * c4;
            *(float2*)(r0p + dc) = make_float2(oacc[nf][0] * inv0, oacc[nf][1] * inv0);
            *(float2*)(r1p + dc) = make_float2(oacc[nf][2] * inv1, oacc[nf][3] * inv1);
        }
    }
}

// ---------------------------------------------------------------------------
// Inputs: hidden f32 [1,4096,2304], mask (ignored — analytic), Wq [2048,2304],
// Wk [1024,2304], Wv [1024,2304], Wo [2304,2048], position_ids i32 [1,4096].
// ---------------------------------------------------------------------------
extern "C" void kernel_launch(void* const* d_in, const int* in_sizes, int n_in,
                              void* d_out, int out_size)
{
    const float* hidden = (const float*)d_in[0];
    const float* Wq     = (const float*)d_in[2];
    const float* Wk     = (const float*)d_in[3];
    const float* Wv     = (const float*)d_in[4];
    const float* Wo     = (const float*)d_in[5];
    const int*   pos    = (const int*)d_in[6];
    float*       out    = (float*)d_out;

    float *qkv, *ao;
    cudaGetSymbolAddress((void**)&qkv, g_qkv);
    cudaGetSymbolAddress((void**)&ao,  g_ao);

    cudaFuncSetAttribute(attn_mma2, cudaFuncAttributeMaxDynamicSharedMemorySize, ATTN_SMEM_BYTES);

    // QKV projections (proven)
    gemm_bf16s<<<dim3(16, 32), 256>>>(hidden, Wq, qkv, HIDDEN, HIDDEN, HIDDEN, QKVN, 0);
    gemm_bf16s<<<dim3(8, 32), 256>>>(hidden, Wk, qkv, HIDDEN, HIDDEN, HIDDEN, QKVN, 2048);
    gemm_bf16s<<<dim3(8, 32), 256>>>(hidden, Wv, qkv, HIDDEN, HIDDEN, HIDDEN, QKVN, 3072);

    // RoPE (proven)
    rope_kernel<<<S_LEN, 128>>>(qkv, pos);

    // One-time K/V hi/lo split into fragment-ready layouts
    prep_split<<<dim3(S_LEN / 32, NKV), 256>>>(qkv);

    // Tensor-core attention, direct-gmem K/V fragments, 2 CTAs/SM
    attn_mma2<<<dim3(S_LEN / 64, NH), 256, ATTN_SMEM_BYTES>>>(qkv, ao);

    // Output projection (proven)
    gemm_bf16s<<<dim3(18, 32), 256>>>(ao, Wo, out, NH * HD, NH * HD, NH * HD, HIDDEN, 0);
}

// round 10
// speedup vs baseline: 1.5609x; 1.5609x over previous
#include <cuda_runtime.h>
#include <cuda_bf16.h>
#include <math.h>
#include <stdint.h>

// Problem constants
#define S_LEN   4096
#define HIDDEN  2304
#define NH      8
#define NKV     4
#define HD      256
#define QKVN    4096
#define SWIN    2048
#define SCALE_F 0.0625f
#define CAP_F   50.0f

// Scratch (device globals)
__device__ float g_qkv[(size_t)S_LEN * QKVN];
__device__ float g_ao[(size_t)S_LEN * (NH * HD)];
// Pre-split K/V (bf16 hi/lo):
//   gK*: [kvh][key 4096][dim-pair 128 u32]
//   gV*: [kvh][dim 256][key-pair 2048 u32]  (transposed)
__device__ uint32_t gKh[(size_t)NKV * S_LEN * 128];
__device__ uint32_t gKl[(size_t)NKV * S_LEN * 128];
__device__ uint32_t gVh[(size_t)NKV * HD * (S_LEN / 2)];
__device__ uint32_t gVl[(size_t)NKV * HD * (S_LEN / 2)];

// ---------------------------------------------------------------------------
// Shared helpers: verified m16n8k16 bf16 mma + hi/lo split
// ---------------------------------------------------------------------------
__device__ __forceinline__ void mma_bf16(float* d,
    uint32_t a0, uint32_t a1, uint32_t a2, uint32_t a3, uint32_t b0, uint32_t b1)
{
    asm volatile(
        "mma.sync.aligned.m16n8k16.row.col.f32.bf16.bf16.f32 "
        "{%0,%1,%2,%3}, {%4,%5,%6,%7}, {%8,%9}, {%0,%1,%2,%3};\n"
        : "+f"(d[0]), "+f"(d[1]), "+f"(d[2]), "+f"(d[3])
        : "r"(a0), "r"(a1), "r"(a2), "r"(a3), "r"(b0), "r"(b1));
}

__device__ __forceinline__ void split2(float x, float y, uint32_t& hi, uint32_t& lo)
{
    __nv_bfloat16 hx = __float2bfloat16_rn(x);
    __nv_bfloat16 hy = __float2bfloat16_rn(y);
    __nv_bfloat16 lx = __float2bfloat16_rn(x - __bfloat162float(hx));
    __nv_bfloat16 ly = __float2bfloat16_rn(y - __bfloat162float(hy));
    __nv_bfloat162 h2 = __halves2bfloat162(hx, hy);
    __nv_bfloat162 l2 = __halves2bfloat162(lx, ly);
    hi = *(uint32_t*)&h2;
    lo = *(uint32_t*)&l2;
}

// ---------------------------------------------------------------------------
// bf16 hi/lo split GEMM (R6/R7-proven)
// ---------------------------------------------------------------------------
#define BSTR 12
#define BBUF (128 * BSTR)

__global__ void __launch_bounds__(256) gemm_bf16s(
    const float* __restrict__ A, const float* __restrict__ B, float* __restrict__ C,
    int K, int lda, int ldb, int ldc, int coff)
{
    __shared__ uint32_t Ah[2][BBUF], Al[2][BBUF];
    __shared__ uint32_t Bh[2][BBUF], Bl[2][BBUF];

    const int tid  = threadIdx.x;
    const int warp = tid >> 5, lane = tid & 31;
    const int g    = lane >> 2, c4 = lane & 3;
    const int wm   = (warp >> 1) * 32, wn = (warp & 1) * 64;
    const int bm   = blockIdx.y * 128, bn = blockIdx.x * 128;

    const int lrow = tid >> 1;
    const int lh   = (tid & 1) * 4;

    const float* Abase = A + (size_t)(bm + lrow) * lda + lh * 2;
    const float* Bbase = B + (size_t)(bn + lrow) * ldb + lh * 2;

    float acc[2][8][4];
#pragma unroll
    for (int i = 0; i < 2; i++)
#pragma unroll
        for (int j = 0; j < 8; j++)
#pragma unroll
            for (int t = 0; t < 4; t++) acc[i][j][t] = 0.f;

    const int nc = K >> 4;
    float4 ra0, ra1, rb0, rb1;

    ra0 = *(const float4*)(Abase);
    ra1 = *(const float4*)(Abase + 4);
    rb0 = *(const float4*)(Bbase);
    rb1 = *(const float4*)(Bbase + 4);
    {
        uint4 uh, ul;
        split2(ra0.x, ra0.y, uh.x, ul.x); split2(ra0.z, ra0.w, uh.y, ul.y);
        split2(ra1.x, ra1.y, uh.z, ul.z); split2(ra1.z, ra1.w, uh.w, ul.w);
        *(uint4*)&Ah[0][lrow * BSTR + lh] = uh;
        *(uint4*)&Al[0][lrow * BSTR + lh] = ul;
        split2(rb0.x, rb0.y, uh.x, ul.x); split2(rb0.z, rb0.w, uh.y, ul.y);
        split2(rb1.x, rb1.y, uh.z, ul.z); split2(rb1.z, rb1.w, uh.w, ul.w);
        *(uint4*)&Bh[0][lrow * BSTR + lh] = uh;
        *(uint4*)&Bl[0][lrow * BSTR + lh] = ul;
    }
    __syncthreads();

    for (int ch = 0; ch < nc; ch++) {
        const int p = ch & 1;
        if (ch + 1 < nc) {
            const float* ap = Abase + (size_t)(ch + 1) * 16;
            const float* bp = Bbase + (size_t)(ch + 1) * 16;
            ra0 = *(const float4*)(ap);
            ra1 = *(const float4*)(ap + 4);
            rb0 = *(const float4*)(bp);
            rb1 = *(const float4*)(bp + 4);
        }

        uint32_t ah[2][4], al[2][4];
#pragma unroll
        for (int i = 0; i < 2; i++) {
            const int r = wm + i * 16 + g;
            ah[i][0] = Ah[p][r * BSTR + c4];       ah[i][1] = Ah[p][(r + 8) * BSTR + c4];
            ah[i][2] = Ah[p][r * BSTR + c4 + 4];   ah[i][3] = Ah[p][(r + 8) * BSTR + c4 + 4];
            al[i][0] = Al[p][r * BSTR + c4];       al[i][1] = Al[p][(r + 8) * BSTR + c4];
            al[i][2] = Al[p][r * BSTR + c4 + 4];   al[i][3] = Al[p][(r + 8) * BSTR + c4 + 4];
        }
#pragma unroll
        for (int j = 0; j < 8; j++) {
            const int n = wn + j * 8 + g;
            uint32_t bh0 = Bh[p][n * BSTR + c4], bh1 = Bh[p][n * BSTR + c4 + 4];
            uint32_t bl0 = Bl[p][n * BSTR + c4], bl1 = Bl[p][n * BSTR + c4 + 4];
#pragma unroll
            for (int i = 0; i < 2; i++) {
                mma_bf16(acc[i][j], ah[i][0], ah[i][1], ah[i][2], ah[i][3], bh0, bh1);
                mma_bf16(acc[i][j], ah[i][0], ah[i][1], ah[i][2], ah[i][3], bl0, bl1);
                mma_bf16(acc[i][j], al[i][0], al[i][1], al[i][2], al[i][3], bh0, bh1);
            }
        }

        if (ch + 1 < nc) {
            const int q = p ^ 1;
            uint4 uh, ul;
            split2(ra0.x, ra0.y, uh.x, ul.x); split2(ra0.z, ra0.w, uh.y, ul.y);
            split2(ra1.x, ra1.y, uh.z, ul.z); split2(ra1.z, ra1.w, uh.w, ul.w);
            *(uint4*)&Ah[q][lrow * BSTR + lh] = uh;
            *(uint4*)&Al[q][lrow * BSTR + lh] = ul;
            split2(rb0.x, rb0.y, uh.x, ul.x); split2(rb0.z, rb0.w, uh.y, ul.y);
            split2(rb1.x, rb1.y, uh.z, ul.z); split2(rb1.z, rb1.w, uh.w, ul.w);
            *(uint4*)&Bh[q][lrow * BSTR + lh] = uh;
            *(uint4*)&Bl[q][lrow * BSTR + lh] = ul;
        }
        __syncthreads();
    }

#pragma unroll
    for (int i = 0; i < 2; i++) {
        const int r0 = bm + wm + i * 16 + g;
#pragma unroll
        for (int j = 0; j < 8; j++) {
            const int cc = coff + bn + wn + j * 8 + c4 * 2;
            *(float2*)(C + (size_t)r0 * ldc + cc)       = make_float2(acc[i][j][0], acc[i][j][1]);
            *(float2*)(C + (size_t)(r0 + 8) * ldc + cc) = make_float2(acc[i][j][2], acc[i][j][3]);
        }
    }
}

// ---------------------------------------------------------------------------
// RoPE (proven).
// ---------------------------------------------------------------------------
__global__ void rope_kernel(float* __restrict__ qkv, const int* __restrict__ pos_ids)
{
    const int s = blockIdx.x;
    const int d = threadIdx.x;
    const double invf = exp(-(double)d * (9.210340371976184 / 128.0));
    const double ang  = (double)pos_ids[s] * invf;
    const float c  = (float)cos(ang);
    const float si = (float)sin(ang);

    float* row = qkv + (size_t)s * QKVN;
#pragma unroll
    for (int head = 0; head < 12; head++) {
        const int base = head * 256;
        const float x0 = row[base + d];
        const float x1 = row[base + d + 128];
        row[base + d]       = x0 * c - x1 * si;
        row[base + d + 128] = x1 * c + x0 * si;
    }
}

// ---------------------------------------------------------------------------
// prep_split (R9-verified): one-time K/V hi/lo split, V transposed.
// ---------------------------------------------------------------------------
__global__ void __launch_bounds__(256) prep_split(const float* __restrict__ qkv)
{
    __shared__ unsigned short sVh[32][260], sVl[32][260];

    const int kvh = blockIdx.y;
    const int kt  = blockIdx.x * 32;
    const int tid = threadIdx.x;
    const int r   = tid >> 3;
    const int cb  = (tid & 7) * 32;

    const float* krow = qkv + (size_t)(kt + r) * QKVN + NH * HD + kvh * HD + cb;
    const float* vrow = krow + NKV * HD;
    uint32_t* khp = gKh + ((size_t)kvh * S_LEN + kt + r) * 128 + cb / 2;
    uint32_t* klp = gKl + ((size_t)kvh * S_LEN + kt + r) * 128 + cb / 2;

#pragma unroll
    for (int i = 0; i < 8; i++) {
        float4 kv = *(const float4*)(krow + i * 4);
        uint32_t h0, l0, h1, l1;
        split2(kv.x, kv.y, h0, l0);
        split2(kv.z, kv.w, h1, l1);
        khp[i * 2] = h0; khp[i * 2 + 1] = h1;
        klp[i * 2] = l0; klp[i * 2 + 1] = l1;

        float4 vv = *(const float4*)(vrow + i * 4);
        uint32_t vh0, vl0, vh1, vl1;
        split2(vv.x, vv.y, vh0, vl0);
        split2(vv.z, vv.w, vh1, vl1);
        *(uint32_t*)&sVh[r][cb + i * 4]     = vh0;
        *(uint32_t*)&sVh[r][cb + i * 4 + 2] = vh1;
        *(uint32_t*)&sVl[r][cb + i * 4]     = vl0;
        *(uint32_t*)&sVl[r][cb + i * 4 + 2] = vl1;
    }
    __syncthreads();

    const int d = tid;
    uint32_t* vhp = gVh + ((size_t)kvh * HD + d) * (S_LEN / 2) + kt / 2;
    uint32_t* vlp = gVl + ((size_t)kvh * HD + d) * (S_LEN / 2) + kt / 2;
#pragma unroll
    for (int j = 0; j < 16; j++) {
        vhp[j] = (uint32_t)sVh[2 * j][d] | ((uint32_t)sVh[2 * j + 1][d] << 16);
        vlp[j] = (uint32_t)sVl[2 * j][d] | ((uint32_t)sVl[2 * j + 1][d] << 16);
    }
}

// ---------------------------------------------------------------------------
// Tensor-core attention v3: smem-staged (R8 structure) but
//  - K/V staged by coalesced u32 copies from pre-split gmem (no split ALU,
//    no transpose in-loop)
//  - V smem XOR-swizzled: idx = dn*16 + (kp ^ (dn & 7))  -> conflict-free
// Smem (u32): Qh/Ql [64][132], Kh/Kl [32][132], Vh/Vl [256][16] swizzled,
// Ph/Pl [64][20].  ~141 KB -> 1 CTA/SM.
// ---------------------------------------------------------------------------
#define AQ_STR 132
#define AP_STR 20
#define QH_OFF 0
#define QL_OFF (64 * AQ_STR)
#define KH_OFF (2 * 64 * AQ_STR)
#define KL_OFF (KH_OFF + 32 * AQ_STR)
#define VH_OFF (KL_OFF + 32 * AQ_STR)
#define VL_OFF (VH_OFF + 256 * 16)
#define PH_OFF (VL_OFF + 256 * 16)
#define PL_OFF (PH_OFF + 64 * AP_STR)
#define ATTN_SMEM_U32 (PL_OFF + 64 * AP_STR)
#define ATTN_SMEM_BYTES (ATTN_SMEM_U32 * 4)

__device__ __forceinline__ float softcap_p(float s, int gq, int gk)
{
    float t = CAP_F * tanhf(s * (1.0f / CAP_F));
    bool ok = (gk <= gq) && ((gq - gk) < SWIN);
    return ok ? __expf(t - CAP_F) : 0.f;
}

__global__ void __launch_bounds__(256) attn_mma3(
    const float* __restrict__ qkv, float* __restrict__ ao)
{
    extern __shared__ uint32_t smA[];
    uint32_t* Qh = smA + QH_OFF;
    uint32_t* Ql = smA + QL_OFF;
    uint32_t* Kh = smA + KH_OFF;
    uint32_t* Kl = smA + KL_OFF;
    uint32_t* Vh = smA + VH_OFF;
    uint32_t* Vl = smA + VL_OFF;
    uint32_t* Ph = smA + PH_OFF;
    uint32_t* Pl = smA + PL_OFF;
    __shared__ float LS[2][64];

    const int h   = blockIdx.y;
    const int q0  = blockIdx.x * 64;
    const int kvh = h >> 1;
    const int tid = threadIdx.x;
    const int warp = tid >> 5, lane = tid & 31;
    const int g = lane >> 2, c4 = lane & 3;
    const int wm  = (warp >> 1) * 16;
    const int wh  = warp & 1;

    // ---- Load Q tile [64 x 256], pre-scaled, split into Qh/Ql ----
    {
        const int row = tid >> 2;
        const int cb  = (tid & 3) * 64;
        const float* qrow = qkv + (size_t)(q0 + row) * QKVN + h * HD + cb;
        uint32_t* qhp = Qh + row * AQ_STR + cb / 2;
        uint32_t* qlp = Ql + row * AQ_STR + cb / 2;
#pragma unroll
        for (int i = 0; i < 16; i++) {
            float4 v = *(const float4*)(qrow + i * 4);
            v.x *= SCALE_F; v.y *= SCALE_F; v.z *= SCALE_F; v.w *= SCALE_F;
            uint32_t h0, l0, h1, l1;
            split2(v.x, v.y, h0, l0);
            split2(v.z, v.w, h1, l1);
            qhp[i * 2] = h0; qhp[i * 2 + 1] = h1;
            qlp[i * 2] = l0; qlp[i * 2 + 1] = l1;
        }
    }

    float oacc[16][4];
#pragma unroll
    for (int nf = 0; nf < 16; nf++)
#pragma unroll
        for (int t = 0; t < 4; t++) oacc[nf][t] = 0.f;
    float lsum0 = 0.f, lsum1 = 0.f;

    int klo = q0 - (SWIN - 1);
    if (klo < 0) klo = 0;
    klo &= ~31;
    const int khi = q0 + 63;

    // staging index precompute
    const int kr  = tid >> 3;            // K stage: key row 0..31
    const int kc0 = (tid & 7) * 16;      // 16 u32 per thread
    const int vj  = tid & 15;            // V stage: key-pair lane
    const int vd0 = tid >> 4;            // V stage: dim group 0..15

    for (int kt = klo; kt <= khi; kt += 32) {
        __syncthreads();   // previous tile's smem fully consumed

        // ---- stage K tile: coalesced u32 copies from gKh/gKl ----
        {
            const uint32_t* skh = gKh + ((size_t)kvh * S_LEN + kt + kr) * 128 + kc0;
            const uint32_t* skl = gKl + ((size_t)kvh * S_LEN + kt + kr) * 128 + kc0;
            uint32_t* dkh = Kh + kr * AQ_STR + kc0;
            uint32_t* dkl = Kl + kr * AQ_STR + kc0;
#pragma unroll
            for (int i = 0; i < 4; i++) {
                *(uint4*)(dkh + i * 4) = *(const uint4*)(skh + i * 4);
                *(uint4*)(dkl + i * 4) = *(const uint4*)(skl + i * 4);
            }
        }
        // ---- stage V tile: swizzled stores, coalesced loads ----
        {
            const size_t vbase = (size_t)kvh * HD * (S_LEN / 2) + (kt >> 1) + vj;
#pragma unroll
            for (int pass = 0; pass < 16; pass++) {
                const int d = pass * 16 + vd0;
                const int idx = d * 16 + (vj ^ (d & 7));
                Vh[idx] = gVh[vbase + (size_t)d * (S_LEN / 2)];
                Vl[idx] = gVl[vbase + (size_t)d * (S_LEN / 2)];
            }
        }
        __syncthreads();

        // ---- S = Q K^T ----
        float sacc[2][4];
#pragma unroll
        for (int f = 0; f < 2; f++)
#pragma unroll
            for (int t = 0; t < 4; t++) sacc[f][t] = 0.f;

#pragma unroll 4
        for (int ks = 0; ks < 16; ks++) {
            const int qa = (wm + g) * AQ_STR + ks * 8 + c4;
            uint32_t ah0 = Qh[qa], ah1 = Qh[qa + 8 * AQ_STR];
            uint32_t ah2 = Qh[qa + 4], ah3 = Qh[qa + 8 * AQ_STR + 4];
            uint32_t al0 = Ql[qa], al1 = Ql[qa + 8 * AQ_STR];
            uint32_t al2 = Ql[qa + 4], al3 = Ql[qa + 8 * AQ_STR + 4];
            const int kb = (wh * 16 + g) * AQ_STR + ks * 8 + c4;
#pragma unroll
            for (int f = 0; f < 2; f++) {
                const int kbf = kb + f * 8 * AQ_STR;
                uint32_t bh0 = Kh[kbf], bh1 = Kh[kbf + 4];
                uint32_t bl0 = Kl[kbf], bl1 = Kl[kbf + 4];
                mma_bf16(sacc[f], ah0, ah1, ah2, ah3, bh0, bh1);
                mma_bf16(sacc[f], ah0, ah1, ah2, ah3, bl0, bl1);
                mma_bf16(sacc[f], al0, al1, al2, al3, bh0, bh1);
            }
        }

        // ---- softmax + pack P ----
        {
            const int r0 = q0 + wm + g;
            const int kb0 = kt + wh * 16 + 2 * c4;
#pragma unroll
            for (int f = 0; f < 2; f++) {
                const int kk = kb0 + f * 8;
                float p00 = softcap_p(sacc[f][0], r0, kk);
                float p01 = softcap_p(sacc[f][1], r0, kk + 1);
                float p10 = softcap_p(sacc[f][2], r0 + 8, kk);
                float p11 = softcap_p(sacc[f][3], r0 + 8, kk + 1);
                lsum0 += p00 + p01;
                lsum1 += p10 + p11;
                uint32_t hi, lo;
                split2(p00, p01, hi, lo);
                Ph[(wm + g) * AP_STR + wh * 8 + f * 4 + c4] = hi;
                Pl[(wm + g) * AP_STR + wh * 8 + f * 4 + c4] = lo;
                split2(p10, p11, hi, lo);
                Ph[(wm + g + 8) * AP_STR + wh * 8 + f * 4 + c4] = hi;
                Pl[(wm + g + 8) * AP_STR + wh * 8 + f * 4 + c4] = lo;
            }
        }
        __syncthreads();

        // ---- O += P V  (V reads conflict-free via swizzle) ----
#pragma unroll
        for (int ks2 = 0; ks2 < 2; ks2++) {
            const int pa = (wm + g) * AP_STR + ks2 * 8 + c4;
            uint32_t pah0 = Ph[pa], pah1 = Ph[pa + 8 * AP_STR];
            uint32_t pah2 = Ph[pa + 4], pah3 = Ph[pa + 8 * AP_STR + 4];
            uint32_t pal0 = Pl[pa], pal1 = Pl[pa + 8 * AP_STR];
            uint32_t pal2 = Pl[pa + 4], pal3 = Pl[pa + 8 * AP_STR + 4];
            const int kp0 = ks2 * 8 + c4;
#pragma unroll
            for (int nf = 0; nf < 16; nf++) {
                const int dn = wh * 128 + nf * 8 + g;
                const int vb = dn * 16;
                const int sw = dn & 7;
                uint32_t vh0 = Vh[vb + (kp0 ^ sw)],       vh1 = Vh[vb + ((kp0 + 4) ^ sw)];
                uint32_t vl0 = Vl[vb + (kp0 ^ sw)],       vl1 = Vl[vb + ((kp0 + 4) ^ sw)];
                mma_bf16(oacc[nf], pah0, pah1, pah2, pah3, vh0, vh1);
                mma_bf16(oacc[nf], pah0, pah1, pah2, pah3, vl0, vl1);
                mma_bf16(oacc[nf], pal0, pal1, pal2, pal3, vh0, vh1);
            }
        }
    }

    // ---- reduce row sums ----
    lsum0 += __shfl_xor_sync(0xffffffffu, lsum0, 1);
    lsum0 += __shfl_xor_sync(0xffffffffu, lsum0, 2);
    lsum1 += __shfl_xor_sync(0xffffffffu, lsum1, 1);
    lsum1 += __shfl_xor_sync(0xffffffffu, lsum1, 2);
    if (c4 == 0) {
        LS[wh][wm + g]     = lsum0;
        LS[wh][wm + g + 8] = lsum1;
    }
    __syncthreads();
    const float inv0 = 1.0f / (LS[0][wm + g] + LS[1][wm + g]);
    const float inv1 = 1.0f / (LS[0][wm + g + 8] + LS[1][wm + g + 8]);

    // ---- store O ----
    {
        float* r0p = ao + (size_t)(q0 + wm + g) * (NH * HD) + h * HD + wh * 128;
        float* r1p = ao + (size_t)(q0 + wm + g + 8) * (NH * HD) + h * HD + wh * 128;
#pragma unroll
        for (int nf = 0; nf < 16; nf++) {
            const int dc = nf * 8 + 2 * c4;
            *(float2*)(r0p + dc) = make_float2(oacc[nf][0] * inv0, oacc[nf][1] * inv0);
            *(float2*)(r1p + dc) = make_float2(oacc[nf][2] * inv1, oacc[nf][3] * inv1);
        }
    }
}

// ---------------------------------------------------------------------------
// Inputs: hidden f32 [1,4096,2304], mask (ignored — analytic), Wq [2048,2304],
// Wk [1024,2304], Wv [1024,2304], Wo [2304,2048], position_ids i32 [1,4096].
// ---------------------------------------------------------------------------
extern "C" void kernel_launch(void* const* d_in, const int* in_sizes, int n_in,
                              void* d_out, int out_size)
{
    const float* hidden = (const float*)d_in[0];
    const float* Wq     = (const float*)d_in[2];
    const float* Wk     = (const float*)d_in[3];
    const float* Wv     = (const float*)d_in[4];
    const float* Wo     = (const float*)d_in[5];
    const int*   pos    = (const int*)d_in[6];
    float*       out    = (float*)d_out;

    float *qkv, *ao;
    cudaGetSymbolAddress((void**)&qkv, g_qkv);
    cudaGetSymbolAddress((void**)&ao,  g_ao);

    cudaFuncSetAttribute(attn_mma3, cudaFuncAttributeMaxDynamicSharedMemorySize, ATTN_SMEM_BYTES);

    // QKV projections (proven)
    gemm_bf16s<<<dim3(16, 32), 256>>>(hidden, Wq, qkv, HIDDEN, HIDDEN, HIDDEN, QKVN, 0);
    gemm_bf16s<<<dim3(8, 32), 256>>>(hidden, Wk, qkv, HIDDEN, HIDDEN, HIDDEN, QKVN, 2048);
    gemm_bf16s<<<dim3(8, 32), 256>>>(hidden, Wv, qkv, HIDDEN, HIDDEN, HIDDEN, QKVN, 3072);

    // RoPE (proven)
    rope_kernel<<<S_LEN, 128>>>(qkv, pos);

    // One-time K/V hi/lo split into copy-ready layouts
    prep_split<<<dim3(S_LEN / 32, NKV), 256>>>(qkv);

    // Tensor-core attention: smem-staged, swizzled V, no in-loop split ALU
    attn_mma3<<<dim3(S_LEN / 64, NH), 256, ATTN_SMEM_BYTES>>>(qkv, ao);

    // Output projection (proven)
    gemm_bf16s<<<dim3(18, 32), 256>>>(ao, Wo, out, NH * HD, NH * HD, NH * HD, HIDDEN, 0);
}

// round 11
// speedup vs baseline: 1.6926x; 1.0843x over previous
#include <cuda_runtime.h>
#include <cuda_bf16.h>
#include <math.h>
#include <stdint.h>

// Problem constants
#define S_LEN   4096
#define HIDDEN  2304
#define NH      8
#define NKV     4
#define HD      256
#define QKVN    4096
#define SWIN    2048
#define SCALE_F 0.0625f
#define CAP_F   50.0f

// Scratch (device globals)
__device__ float g_qkv[(size_t)S_LEN * QKVN];
__device__ float g_ao[(size_t)S_LEN * (NH * HD)];
// Pre-split K/V (bf16 hi/lo):
//   gK*: [kvh][key 4096][dim-pair 128 u32]
//   gV*: [kvh][dim 256][key-pair 2048 u32]  (transposed)
__device__ uint32_t gKh[(size_t)NKV * S_LEN * 128];
__device__ uint32_t gKl[(size_t)NKV * S_LEN * 128];
__device__ uint32_t gVh[(size_t)NKV * HD * (S_LEN / 2)];
__device__ uint32_t gVl[(size_t)NKV * HD * (S_LEN / 2)];

// ---------------------------------------------------------------------------
// Shared helpers
// ---------------------------------------------------------------------------
__device__ __forceinline__ void mma_bf16(float* d,
    uint32_t a0, uint32_t a1, uint32_t a2, uint32_t a3, uint32_t b0, uint32_t b1)
{
    asm volatile(
        "mma.sync.aligned.m16n8k16.row.col.f32.bf16.bf16.f32 "
        "{%0,%1,%2,%3}, {%4,%5,%6,%7}, {%8,%9}, {%0,%1,%2,%3};\n"
        : "+f"(d[0]), "+f"(d[1]), "+f"(d[2]), "+f"(d[3])
        : "r"(a0), "r"(a1), "r"(a2), "r"(a3), "r"(b0), "r"(b1));
}

__device__ __forceinline__ void split2(float x, float y, uint32_t& hi, uint32_t& lo)
{
    __nv_bfloat16 hx = __float2bfloat16_rn(x);
    __nv_bfloat16 hy = __float2bfloat16_rn(y);
    __nv_bfloat16 lx = __float2bfloat16_rn(x - __bfloat162float(hx));
    __nv_bfloat16 ly = __float2bfloat16_rn(y - __bfloat162float(hy));
    __nv_bfloat162 h2 = __halves2bfloat162(hx, hy);
    __nv_bfloat162 l2 = __halves2bfloat162(lx, ly);
    hi = *(uint32_t*)&h2;
    lo = *(uint32_t*)&l2;
}

__device__ __forceinline__ void cpa16(uint32_t dst_smem, const uint32_t* src)
{
    asm volatile("cp.async.ca.shared.global [%0], [%1], 16;\n"
                 :: "r"(dst_smem), "l"(src));
}

// ---------------------------------------------------------------------------
// bf16 hi/lo split GEMM (R6/R7-proven)
// ---------------------------------------------------------------------------
#define BSTR 12
#define BBUF (128 * BSTR)

__global__ void __launch_bounds__(256) gemm_bf16s(
    const float* __restrict__ A, const float* __restrict__ B, float* __restrict__ C,
    int K, int lda, int ldb, int ldc, int coff)
{
    __shared__ uint32_t Ah[2][BBUF], Al[2][BBUF];
    __shared__ uint32_t Bh[2][BBUF], Bl[2][BBUF];

    const int tid  = threadIdx.x;
    const int warp = tid >> 5, lane = tid & 31;
    const int g    = lane >> 2, c4 = lane & 3;
    const int wm   = (warp >> 1) * 32, wn = (warp & 1) * 64;
    const int bm   = blockIdx.y * 128, bn = blockIdx.x * 128;

    const int lrow = tid >> 1;
    const int lh   = (tid & 1) * 4;

    const float* Abase = A + (size_t)(bm + lrow) * lda + lh * 2;
    const float* Bbase = B + (size_t)(bn + lrow) * ldb + lh * 2;

    float acc[2][8][4];
#pragma unroll
    for (int i = 0; i < 2; i++)
#pragma unroll
        for (int j = 0; j < 8; j++)
#pragma unroll
            for (int t = 0; t < 4; t++) acc[i][j][t] = 0.f;

    const int nc = K >> 4;
    float4 ra0, ra1, rb0, rb1;

    ra0 = *(const float4*)(Abase);
    ra1 = *(const float4*)(Abase + 4);
    rb0 = *(const float4*)(Bbase);
    rb1 = *(const float4*)(Bbase + 4);
    {
        uint4 uh, ul;
        split2(ra0.x, ra0.y, uh.x, ul.x); split2(ra0.z, ra0.w, uh.y, ul.y);
        split2(ra1.x, ra1.y, uh.z, ul.z); split2(ra1.z, ra1.w, uh.w, ul.w);
        *(uint4*)&Ah[0][lrow * BSTR + lh] = uh;
        *(uint4*)&Al[0][lrow * BSTR + lh] = ul;
        split2(rb0.x, rb0.y, uh.x, ul.x); split2(rb0.z, rb0.w, uh.y, ul.y);
        split2(rb1.x, rb1.y, uh.z, ul.z); split2(rb1.z, rb1.w, uh.w, ul.w);
        *(uint4*)&Bh[0][lrow * BSTR + lh] = uh;
        *(uint4*)&Bl[0][lrow * BSTR + lh] = ul;
    }
    __syncthreads();

    for (int ch = 0; ch < nc; ch++) {
        const int p = ch & 1;
        if (ch + 1 < nc) {
            const float* ap = Abase + (size_t)(ch + 1) * 16;
            const float* bp = Bbase + (size_t)(ch + 1) * 16;
            ra0 = *(const float4*)(ap);
            ra1 = *(const float4*)(ap + 4);
            rb0 = *(const float4*)(bp);
            rb1 = *(const float4*)(bp + 4);
        }

        uint32_t ah[2][4], al[2][4];
#pragma unroll
        for (int i = 0; i < 2; i++) {
            const int r = wm + i * 16 + g;
            ah[i][0] = Ah[p][r * BSTR + c4];       ah[i][1] = Ah[p][(r + 8) * BSTR + c4];
            ah[i][2] = Ah[p][r * BSTR + c4 + 4];   ah[i][3] = Ah[p][(r + 8) * BSTR + c4 + 4];
            al[i][0] = Al[p][r * BSTR + c4];       al[i][1] = Al[p][(r + 8) * BSTR + c4];
            al[i][2] = Al[p][r * BSTR + c4 + 4];   al[i][3] = Al[p][(r + 8) * BSTR + c4 + 4];
        }
#pragma unroll
        for (int j = 0; j < 8; j++) {
            const int n = wn + j * 8 + g;
            uint32_t bh0 = Bh[p][n * BSTR + c4], bh1 = Bh[p][n * BSTR + c4 + 4];
            uint32_t bl0 = Bl[p][n * BSTR + c4], bl1 = Bl[p][n * BSTR + c4 + 4];
#pragma unroll
            for (int i = 0; i < 2; i++) {
                mma_bf16(acc[i][j], ah[i][0], ah[i][1], ah[i][2], ah[i][3], bh0, bh1);
                mma_bf16(acc[i][j], ah[i][0], ah[i][1], ah[i][2], ah[i][3], bl0, bl1);
                mma_bf16(acc[i][j], al[i][0], al[i][1], al[i][2], al[i][3], bh0, bh1);
            }
        }

        if (ch + 1 < nc) {
            const int q = p ^ 1;
            uint4 uh, ul;
            split2(ra0.x, ra0.y, uh.x, ul.x); split2(ra0.z, ra0.w, uh.y, ul.y);
            split2(ra1.x, ra1.y, uh.z, ul.z); split2(ra1.z, ra1.w, uh.w, ul.w);
            *(uint4*)&Ah[q][lrow * BSTR + lh] = uh;
            *(uint4*)&Al[q][lrow * BSTR + lh] = ul;
            split2(rb0.x, rb0.y, uh.x, ul.x); split2(rb0.z, rb0.w, uh.y, ul.y);
            split2(rb1.x, rb1.y, uh.z, ul.z); split2(rb1.z, rb1.w, uh.w, ul.w);
            *(uint4*)&Bh[q][lrow * BSTR + lh] = uh;
            *(uint4*)&Bl[q][lrow * BSTR + lh] = ul;
        }
        __syncthreads();
    }

#pragma unroll
    for (int i = 0; i < 2; i++) {
        const int r0 = bm + wm + i * 16 + g;
#pragma unroll
        for (int j = 0; j < 8; j++) {
            const int cc = coff + bn + wn + j * 8 + c4 * 2;
            *(float2*)(C + (size_t)r0 * ldc + cc)       = make_float2(acc[i][j][0], acc[i][j][1]);
            *(float2*)(C + (size_t)(r0 + 8) * ldc + cc) = make_float2(acc[i][j][2], acc[i][j][3]);
        }
    }
}

// ---------------------------------------------------------------------------
// RoPE (proven).
// ---------------------------------------------------------------------------
__global__ void rope_kernel(float* __restrict__ qkv, const int* __restrict__ pos_ids)
{
    const int s = blockIdx.x;
    const int d = threadIdx.x;
    const double invf = exp(-(double)d * (9.210340371976184 / 128.0));
    const double ang  = (double)pos_ids[s] * invf;
    const float c  = (float)cos(ang);
    const float si = (float)sin(ang);

    float* row = qkv + (size_t)s * QKVN;
#pragma unroll
    for (int head = 0; head < 12; head++) {
        const int base = head * 256;
        const float x0 = row[base + d];
        const float x1 = row[base + d + 128];
        row[base + d]       = x0 * c - x1 * si;
        row[base + d + 128] = x1 * c + x0 * si;
    }
}

// ---------------------------------------------------------------------------
// prep_split (proven): one-time K/V hi/lo split, V transposed.
// ---------------------------------------------------------------------------
__global__ void __launch_bounds__(256) prep_split(const float* __restrict__ qkv)
{
    __shared__ unsigned short sVh[32][260], sVl[32][260];

    const int kvh = blockIdx.y;
    const int kt  = blockIdx.x * 32;
    const int tid = threadIdx.x;
    const int r   = tid >> 3;
    const int cb  = (tid & 7) * 32;

    const float* krow = qkv + (size_t)(kt + r) * QKVN + NH * HD + kvh * HD + cb;
    const float* vrow = krow + NKV * HD;
    uint32_t* khp = gKh + ((size_t)kvh * S_LEN + kt + r) * 128 + cb / 2;
    uint32_t* klp = gKl + ((size_t)kvh * S_LEN + kt + r) * 128 + cb / 2;

#pragma unroll
    for (int i = 0; i < 8; i++) {
        float4 kv = *(const float4*)(krow + i * 4);
        uint32_t h0, l0, h1, l1;
        split2(kv.x, kv.y, h0, l0);
        split2(kv.z, kv.w, h1, l1);
        khp[i * 2] = h0; khp[i * 2 + 1] = h1;
        klp[i * 2] = l0; klp[i * 2 + 1] = l1;

        float4 vv = *(const float4*)(vrow + i * 4);
        uint32_t vh0, vl0, vh1, vl1;
        split2(vv.x, vv.y, vh0, vl0);
        split2(vv.z, vv.w, vh1, vl1);
        *(uint32_t*)&sVh[r][cb + i * 4]     = vh0;
        *(uint32_t*)&sVh[r][cb + i * 4 + 2] = vh1;
        *(uint32_t*)&sVl[r][cb + i * 4]     = vl0;
        *(uint32_t*)&sVl[r][cb + i * 4 + 2] = vl1;
    }
    __syncthreads();

    const int d = tid;
    uint32_t* vhp = gVh + ((size_t)kvh * HD + d) * (S_LEN / 2) + kt / 2;
    uint32_t* vlp = gVl + ((size_t)kvh * HD + d) * (S_LEN / 2) + kt / 2;
#pragma unroll
    for (int j = 0; j < 16; j++) {
        vhp[j] = (uint32_t)sVh[2 * j][d] | ((uint32_t)sVh[2 * j + 1][d] << 16);
        vlp[j] = (uint32_t)sVl[2 * j][d] | ((uint32_t)sVl[2 * j + 1][d] << 16);
    }
}

// ---------------------------------------------------------------------------
// Tensor-core attention v4: cp.async double-buffered K/V staging.
//  - next tile's K/V issued (LDGSTS) before computing current tile;
//    wait_group(1) retires the previous group -> staging latency hidden
//  - V swizzle at 16B granularity: idx = d*16 + 4*(group ^ ((d>>1)&3)) + w
//    (cp.async dst contiguous; PV LDS conflict-free across g-lanes)
// Smem (u32): Qh/Ql [64][132]; K 2 bufs x (Kh+Kl)[32][132];
//             V 2 bufs x (Vh+Vl)[256][16] swizzled; Ph/Pl [64][20]. 206 KB.
// ---------------------------------------------------------------------------
#define AQ_STR 132
#define AP_STR 20
#define QH_OFF 0
#define QL_OFF (64 * AQ_STR)                 // 8448
#define K_OFF  (2 * 64 * AQ_STR)             // 16896
#define KBUF_STR (2 * 32 * AQ_STR)           // 8448 per buffer (Kh+Kl)
#define V_OFF  (K_OFF + 2 * KBUF_STR)        // 33792
#define VBUF_STR (2 * 256 * 16)              // 8192 per buffer (Vh+Vl)
#define P_OFF  (V_OFF + 2 * VBUF_STR)        // 50176
#define ATTN_SMEM_U32 (P_OFF + 2 * 64 * AP_STR)
#define ATTN_SMEM_BYTES (ATTN_SMEM_U32 * 4)  // 210944

__device__ __forceinline__ float softcap_p(float s, int gq, int gk)
{
    float t = CAP_F * tanhf(s * (1.0f / CAP_F));
    bool ok = (gk <= gq) && ((gq - gk) < SWIN);
    return ok ? __expf(t - CAP_F) : 0.f;
}

__global__ void __launch_bounds__(256) attn_mma4(
    const float* __restrict__ qkv, float* __restrict__ ao)
{
    extern __shared__ uint32_t smA[];
    uint32_t* Qh = smA + QH_OFF;
    uint32_t* Ql = smA + QL_OFF;
    uint32_t* Ph = smA + P_OFF;
    uint32_t* Pl = smA + P_OFF + 64 * AP_STR;
    __shared__ float LS[2][64];

    const uint32_t smem_u32 = (uint32_t)__cvta_generic_to_shared(smA);

    const int h   = blockIdx.y;
    const int q0  = blockIdx.x * 64;
    const int kvh = h >> 1;
    const int tid = threadIdx.x;
    const int warp = tid >> 5, lane = tid & 31;
    const int g = lane >> 2, c4 = lane & 3;
    const int wm  = (warp >> 1) * 16;
    const int wh  = warp & 1;

    // staging index precompute (cp.async)
    const int kr  = tid >> 3;                 // K: key row 0..31
    const int kc  = (tid & 7) * 4;            // K: u32 offset of first 16B chunk
    const int vdg = tid >> 2;                 // V: dim sub-row 0..63
    const int vgp = tid & 3;                  // V: key-pair group 0..3
    const uint32_t* skh_b = gKh + ((size_t)kvh * S_LEN + kr) * 128 + kc;
    const uint32_t* skl_b = gKl + ((size_t)kvh * S_LEN + kr) * 128 + kc;
    const uint32_t* svh_b = gVh + ((size_t)kvh * HD) * (S_LEN / 2) + vgp * 4;
    const uint32_t* svl_b = gVl + ((size_t)kvh * HD) * (S_LEN / 2) + vgp * 4;

    // ---- Load Q tile [64 x 256], pre-scaled, split into Qh/Ql ----
    {
        const int row = tid >> 2;
        const int cb  = (tid & 3) * 64;
        const float* qrow = qkv + (size_t)(q0 + row) * QKVN + h * HD + cb;
        uint32_t* qhp = Qh + row * AQ_STR + cb / 2;
        uint32_t* qlp = Ql + row * AQ_STR + cb / 2;
#pragma unroll
        for (int i = 0; i < 16; i++) {
            float4 v = *(const float4*)(qrow + i * 4);
            v.x *= SCALE_F; v.y *= SCALE_F; v.z *= SCALE_F; v.w *= SCALE_F;
            uint32_t h0, l0, h1, l1;
            split2(v.x, v.y, h0, l0);
            split2(v.z, v.w, h1, l1);
            qhp[i * 2] = h0; qhp[i * 2 + 1] = h1;
            qlp[i * 2] = l0; qlp[i * 2 + 1] = l1;
        }
    }

    float oacc[16][4];
#pragma unroll
    for (int nf = 0; nf < 16; nf++)
#pragma unroll
        for (int t = 0; t < 4; t++) oacc[nf][t] = 0.f;
    float lsum0 = 0.f, lsum1 = 0.f;

    int klo = q0 - (SWIN - 1);
    if (klo < 0) klo = 0;
    klo &= ~31;
    const int khi = q0 + 63;

    // issue tile staging into buffer b (16 cp.async of 16B per thread)
    auto stage = [&](int kt_, int b) {
        const uint32_t kh_d = smem_u32 + (K_OFF + b * KBUF_STR + kr * AQ_STR + kc) * 4;
        const uint32_t kl_d = kh_d + (32 * AQ_STR) * 4;
        const uint32_t* skh = skh_b + (size_t)kt_ * 128;
        const uint32_t* skl = skl_b + (size_t)kt_ * 128;
#pragma unroll
        for (int i = 0; i < 4; i++) {
            cpa16(kh_d + i * 128, skh + i * 32);   // 32 u32 = 128B stride in both
            cpa16(kl_d + i * 128, skl + i * 32);
        }
        const uint32_t* svh = svh_b + (kt_ >> 1);
        const uint32_t* svl = svl_b + (kt_ >> 1);
#pragma unroll
        for (int pass = 0; pass < 4; pass++) {
            const int d = pass * 64 + vdg;
            const int idx = d * 16 + 4 * (vgp ^ ((d >> 1) & 3));
            const uint32_t vh_d = smem_u32 + (V_OFF + b * VBUF_STR + idx) * 4;
            const uint32_t vl_d = vh_d + (256 * 16) * 4;
            cpa16(vh_d, svh + (size_t)d * (S_LEN / 2));
            cpa16(vl_d, svl + (size_t)d * (S_LEN / 2));
        }
        asm volatile("cp.async.commit_group;\n" ::: "memory");
    };

    // prologue: stage first tile into buffer 0
    stage(klo, 0);

    int ti = 0;
    for (int kt = klo; kt <= khi; kt += 32, ti++) {
        __syncthreads();   // all warps done reading buf (ti+1)&1 (prev compute)
        const bool more = (kt + 32 <= khi);
        if (more) {
            stage(kt + 32, (ti + 1) & 1);
            asm volatile("cp.async.wait_group 1;\n" ::: "memory");
        } else {
            asm volatile("cp.async.wait_group 0;\n" ::: "memory");
        }
        __syncthreads();   // tile kt's K/V visible to all

        const uint32_t* Kh = smA + K_OFF + (ti & 1) * KBUF_STR;
        const uint32_t* Kl = Kh + 32 * AQ_STR;
        const uint32_t* Vh = smA + V_OFF + (ti & 1) * VBUF_STR;
        const uint32_t* Vl = Vh + 256 * 16;

        // ---- S = Q K^T ----
        float sacc[2][4];
#pragma unroll
        for (int f = 0; f < 2; f++)
#pragma unroll
            for (int t = 0; t < 4; t++) sacc[f][t] = 0.f;

#pragma unroll 4
        for (int ks = 0; ks < 16; ks++) {
            const int qa = (wm + g) * AQ_STR + ks * 8 + c4;
            uint32_t ah0 = Qh[qa], ah1 = Qh[qa + 8 * AQ_STR];
            uint32_t ah2 = Qh[qa + 4], ah3 = Qh[qa + 8 * AQ_STR + 4];
            uint32_t al0 = Ql[qa], al1 = Ql[qa + 8 * AQ_STR];
            uint32_t al2 = Ql[qa + 4], al3 = Ql[qa + 8 * AQ_STR + 4];
            const int kb = (wh * 16 + g) * AQ_STR + ks * 8 + c4;
#pragma unroll
            for (int f = 0; f < 2; f++) {
                const int kbf = kb + f * 8 * AQ_STR;
                uint32_t bh0 = Kh[kbf], bh1 = Kh[kbf + 4];
                uint32_t bl0 = Kl[kbf], bl1 = Kl[kbf + 4];
                mma_bf16(sacc[f], ah0, ah1, ah2, ah3, bh0, bh1);
                mma_bf16(sacc[f], ah0, ah1, ah2, ah3, bl0, bl1);
                mma_bf16(sacc[f], al0, al1, al2, al3, bh0, bh1);
            }
        }

        // ---- softmax + pack P ----
        {
            const int r0 = q0 + wm + g;
            const int kb0 = kt + wh * 16 + 2 * c4;
#pragma unroll
            for (int f = 0; f < 2; f++) {
                const int kk = kb0 + f * 8;
                float p00 = softcap_p(sacc[f][0], r0, kk);
                float p01 = softcap_p(sacc[f][1], r0, kk + 1);
                float p10 = softcap_p(sacc[f][2], r0 + 8, kk);
                float p11 = softcap_p(sacc[f][3], r0 + 8, kk + 1);
                lsum0 += p00 + p01;
                lsum1 += p10 + p11;
                uint32_t hi, lo;
                split2(p00, p01, hi, lo);
                Ph[(wm + g) * AP_STR + wh * 8 + f * 4 + c4] = hi;
                Pl[(wm + g) * AP_STR + wh * 8 + f * 4 + c4] = lo;
                split2(p10, p11, hi, lo);
                Ph[(wm + g + 8) * AP_STR + wh * 8 + f * 4 + c4] = hi;
                Pl[(wm + g + 8) * AP_STR + wh * 8 + f * 4 + c4] = lo;
            }
        }
        __syncthreads();

        // ---- O += P V  (16B-group swizzle, conflict-free) ----
#pragma unroll
        for (int ks2 = 0; ks2 < 2; ks2++) {
            const int pa = (wm + g) * AP_STR + ks2 * 8 + c4;
            uint32_t pah0 = Ph[pa], pah1 = Ph[pa + 8 * AP_STR];
            uint32_t pah2 = Ph[pa + 4], pah3 = Ph[pa + 8 * AP_STR + 4];
            uint32_t pal0 = Pl[pa], pal1 = Pl[pa + 8 * AP_STR];
            uint32_t pal2 = Pl[pa + 4], pal3 = Pl[pa + 8 * AP_STR + 4];
#pragma unroll
            for (int nf = 0; nf < 16; nf++) {
                const int dn = wh * 128 + nf * 8 + g;
                const int vb = dn * 16;
                const int sw = (dn >> 1) & 3;
                const int i0 = vb + 4 * ((2 * ks2) ^ sw) + c4;
                const int i1 = vb + 4 * ((2 * ks2 + 1) ^ sw) + c4;
                uint32_t vh0 = Vh[i0], vh1 = Vh[i1];
                uint32_t vl0 = Vl[i0], vl1 = Vl[i1];
                mma_bf16(oacc[nf], pah0, pah1, pah2, pah3, vh0, vh1);
                mma_bf16(oacc[nf], pah0, pah1, pah2, pah3, vl0, vl1);
                mma_bf16(oacc[nf], pal0, pal1, pal2, pal3, vh0, vh1);
            }
        }
    }

    // ---- reduce row sums ----
    lsum0 += __shfl_xor_sync(0xffffffffu, lsum0, 1);
    lsum0 += __shfl_xor_sync(0xffffffffu, lsum0, 2);
    lsum1 += __shfl_xor_sync(0xffffffffu, lsum1, 1);
    lsum1 += __shfl_xor_sync(0xffffffffu, lsum1, 2);
    if (c4 == 0) {
        LS[wh][wm + g]     = lsum0;
        LS[wh][wm + g + 8] = lsum1;
    }
    __syncthreads();
    const float inv0 = 1.0f / (LS[0][wm + g] + LS[1][wm + g]);
    const float inv1 = 1.0f / (LS[0][wm + g + 8] + LS[1][wm + g + 8]);

    // ---- store O ----
    {
        float* r0p = ao + (size_t)(q0 + wm + g) * (NH * HD) + h * HD + wh * 128;
        float* r1p = ao + (size_t)(q0 + wm + g + 8) * (NH * HD) + h * HD + wh * 128;
#pragma unroll
        for (int nf = 0; nf < 16; nf++) {
            const int dc = nf * 8 + 2 * c4;
            *(float2*)(r0p + dc) = make_float2(oacc[nf][0] * inv0, oacc[nf][1] * inv0);
            *(float2*)(r1p + dc) = make_float2(oacc[nf][2] * inv1, oacc[nf][3] * inv1);
        }
    }
}

// ---------------------------------------------------------------------------
// Inputs: hidden f32 [1,4096,2304], mask (ignored — analytic), Wq [2048,2304],
// Wk [1024,2304], Wv [1024,2304], Wo [2304,2048], position_ids i32 [1,4096].
// ---------------------------------------------------------------------------
extern "C" void kernel_launch(void* const* d_in, const int* in_sizes, int n_in,
                              void* d_out, int out_size)
{
    const float* hidden = (const float*)d_in[0];
    const float* Wq     = (const float*)d_in[2];
    const float* Wk     = (const float*)d_in[3];
    const float* Wv     = (const float*)d_in[4];
    const float* Wo     = (const float*)d_in[5];
    const int*   pos    = (const int*)d_in[6];
    float*       out    = (float*)d_out;

    float *qkv, *ao;
    cudaGetSymbolAddress((void**)&qkv, g_qkv);
    cudaGetSymbolAddress((void**)&ao,  g_ao);

    cudaFuncSetAttribute(attn_mma4, cudaFuncAttributeMaxDynamicSharedMemorySize, ATTN_SMEM_BYTES);

    // QKV projections (proven)
    gemm_bf16s<<<dim3(16, 32), 256>>>(hidden, Wq, qkv, HIDDEN, HIDDEN, HIDDEN, QKVN, 0);
    gemm_bf16s<<<dim3(8, 32), 256>>>(hidden, Wk, qkv, HIDDEN, HIDDEN, HIDDEN, QKVN, 2048);
    gemm_bf16s<<<dim3(8, 32), 256>>>(hidden, Wv, qkv, HIDDEN, HIDDEN, HIDDEN, QKVN, 3072);

    // RoPE (proven)
    rope_kernel<<<S_LEN, 128>>>(qkv, pos);

    // One-time K/V hi/lo split into copy-ready layouts
    prep_split<<<dim3(S_LEN / 32, NKV), 256>>>(qkv);

    // Tensor-core attention: cp.async double-buffered K/V staging
    attn_mma4<<<dim3(S_LEN / 64, NH), 256, ATTN_SMEM_BYTES>>>(qkv, ao);

    // Output projection (proven)
    gemm_bf16s<<<dim3(18, 32), 256>>>(ao, Wo, out, NH * HD, NH * HD, NH * HD, HIDDEN, 0);
}

// round 13
// speedup vs baseline: 1.7672x; 1.0441x over previous
#include <cuda_runtime.h>
#include <cuda_bf16.h>
#include <math.h>
#include <stdint.h>

// Problem constants
#define S_LEN   4096
#define HIDDEN  2304
#define NH      8
#define NKV     4
#define HD      256
#define QKVN    4096
#define SWIN    2048
#define SCALE_F 0.0625f
#define CAP_F   50.0f

// Scratch (device globals)
__device__ float g_qkv[(size_t)S_LEN * QKVN];
__device__ float g_ao[(size_t)S_LEN * (NH * HD)];
// Pre-split K/V (bf16 hi/lo):
//   gK*: [kvh][key 4096][dim-pair 128 u32]
//   gV*: [kvh][dim 256][key-pair 2048 u32]  (transposed)
__device__ uint32_t gKh[(size_t)NKV * S_LEN * 128];
__device__ uint32_t gKl[(size_t)NKV * S_LEN * 128];
__device__ uint32_t gVh[(size_t)NKV * HD * (S_LEN / 2)];
__device__ uint32_t gVl[(size_t)NKV * HD * (S_LEN / 2)];

// ---------------------------------------------------------------------------
// Shared helpers
// ---------------------------------------------------------------------------
__device__ __forceinline__ void mma_bf16(float* d,
    uint32_t a0, uint32_t a1, uint32_t a2, uint32_t a3, uint32_t b0, uint32_t b1)
{
    asm volatile(
        "mma.sync.aligned.m16n8k16.row.col.f32.bf16.bf16.f32 "
        "{%0,%1,%2,%3}, {%4,%5,%6,%7}, {%8,%9}, {%0,%1,%2,%3};\n"
        : "+f"(d[0]), "+f"(d[1]), "+f"(d[2]), "+f"(d[3])
        : "r"(a0), "r"(a1), "r"(a2), "r"(a3), "r"(b0), "r"(b1));
}

__device__ __forceinline__ void split2(float x, float y, uint32_t& hi, uint32_t& lo)
{
    __nv_bfloat16 hx = __float2bfloat16_rn(x);
    __nv_bfloat16 hy = __float2bfloat16_rn(y);
    __nv_bfloat16 lx = __float2bfloat16_rn(x - __bfloat162float(hx));
    __nv_bfloat16 ly = __float2bfloat16_rn(y - __bfloat162float(hy));
    __nv_bfloat162 h2 = __halves2bfloat162(hx, hy);
    __nv_bfloat162 l2 = __halves2bfloat162(lx, ly);
    hi = *(uint32_t*)&h2;
    lo = *(uint32_t*)&l2;
}

__device__ __forceinline__ void cpa16(uint32_t dst_smem, const uint32_t* src)
{
    asm volatile("cp.async.ca.shared.global [%0], [%1], 16;\n"
                 :: "r"(dst_smem), "l"(src));
}

__device__ __forceinline__ float ex2_approx(float x)
{
    float r;
    asm("ex2.approx.f32 %0, %1;" : "=f"(r) : "f"(x));
    return r;
}

__device__ __forceinline__ float rcp_approx(float x)
{
    float r;
    asm("rcp.approx.f32 %0, %1;" : "=f"(r) : "f"(x));
    return r;
}

// ---------------------------------------------------------------------------
// bf16 hi/lo split GEMM (R6/R7-proven)
// ---------------------------------------------------------------------------
#define BSTR 12
#define BBUF (128 * BSTR)

__global__ void __launch_bounds__(256) gemm_bf16s(
    const float* __restrict__ A, const float* __restrict__ B, float* __restrict__ C,
    int K, int lda, int ldb, int ldc, int coff)
{
    __shared__ uint32_t Ah[2][BBUF], Al[2][BBUF];
    __shared__ uint32_t Bh[2][BBUF], Bl[2][BBUF];

    const int tid  = threadIdx.x;
    const int warp = tid >> 5, lane = tid & 31;
    const int g    = lane >> 2, c4 = lane & 3;
    const int wm   = (warp >> 1) * 32, wn = (warp & 1) * 64;
    const int bm   = blockIdx.y * 128, bn = blockIdx.x * 128;

    const int lrow = tid >> 1;
    const int lh   = (tid & 1) * 4;

    const float* Abase = A + (size_t)(bm + lrow) * lda + lh * 2;
    const float* Bbase = B + (size_t)(bn + lrow) * ldb + lh * 2;

    float acc[2][8][4];
#pragma unroll
    for (int i = 0; i < 2; i++)
#pragma unroll
        for (int j = 0; j < 8; j++)
#pragma unroll
            for (int t = 0; t < 4; t++) acc[i][j][t] = 0.f;

    const int nc = K >> 4;
    float4 ra0, ra1, rb0, rb1;

    ra0 = *(const float4*)(Abase);
    ra1 = *(const float4*)(Abase + 4);
    rb0 = *(const float4*)(Bbase);
    rb1 = *(const float4*)(Bbase + 4);
    {
        uint4 uh, ul;
        split2(ra0.x, ra0.y, uh.x, ul.x); split2(ra0.z, ra0.w, uh.y, ul.y);
        split2(ra1.x, ra1.y, uh.z, ul.z); split2(ra1.z, ra1.w, uh.w, ul.w);
        *(uint4*)&Ah[0][lrow * BSTR + lh] = uh;
        *(uint4*)&Al[0][lrow * BSTR + lh] = ul;
        split2(rb0.x, rb0.y, uh.x, ul.x); split2(rb0.z, rb0.w, uh.y, ul.y);
        split2(rb1.x, rb1.y, uh.z, ul.z); split2(rb1.z, rb1.w, uh.w, ul.w);
        *(uint4*)&Bh[0][lrow * BSTR + lh] = uh;
        *(uint4*)&Bl[0][lrow * BSTR + lh] = ul;
    }
    __syncthreads();

    for (int ch = 0; ch < nc; ch++) {
        const int p = ch & 1;
        if (ch + 1 < nc) {
            const float* ap = Abase + (size_t)(ch + 1) * 16;
            const float* bp = Bbase + (size_t)(ch + 1) * 16;
            ra0 = *(const float4*)(ap);
            ra1 = *(const float4*)(ap + 4);
            rb0 = *(const float4*)(bp);
            rb1 = *(const float4*)(bp + 4);
        }

        uint32_t ah[2][4], al[2][4];
#pragma unroll
        for (int i = 0; i < 2; i++) {
            const int r = wm + i * 16 + g;
            ah[i][0] = Ah[p][r * BSTR + c4];       ah[i][1] = Ah[p][(r + 8) * BSTR + c4];
            ah[i][2] = Ah[p][r * BSTR + c4 + 4];   ah[i][3] = Ah[p][(r + 8) * BSTR + c4 + 4];
            al[i][0] = Al[p][r * BSTR + c4];       al[i][1] = Al[p][(r + 8) * BSTR + c4];
            al[i][2] = Al[p][r * BSTR + c4 + 4];   al[i][3] = Al[p][(r + 8) * BSTR + c4 + 4];
        }
#pragma unroll
        for (int j = 0; j < 8; j++) {
            const int n = wn + j * 8 + g;
            uint32_t bh0 = Bh[p][n * BSTR + c4], bh1 = Bh[p][n * BSTR + c4 + 4];
            uint32_t bl0 = Bl[p][n * BSTR + c4], bl1 = Bl[p][n * BSTR + c4 + 4];
#pragma unroll
            for (int i = 0; i < 2; i++) {
                mma_bf16(acc[i][j], ah[i][0], ah[i][1], ah[i][2], ah[i][3], bh0, bh1);
                mma_bf16(acc[i][j], ah[i][0], ah[i][1], ah[i][2], ah[i][3], bl0, bl1);
                mma_bf16(acc[i][j], al[i][0], al[i][1], al[i][2], al[i][3], bh0, bh1);
            }
        }

        if (ch + 1 < nc) {
            const int q = p ^ 1;
            uint4 uh, ul;
            split2(ra0.x, ra0.y, uh.x, ul.x); split2(ra0.z, ra0.w, uh.y, ul.y);
            split2(ra1.x, ra1.y, uh.z, ul.z); split2(ra1.z, ra1.w, uh.w, ul.w);
            *(uint4*)&Ah[q][lrow * BSTR + lh] = uh;
            *(uint4*)&Al[q][lrow * BSTR + lh] = ul;
            split2(rb0.x, rb0.y, uh.x, ul.x); split2(rb0.z, rb0.w, uh.y, ul.y);
            split2(rb1.x, rb1.y, uh.z, ul.z); split2(rb1.z, rb1.w, uh.w, ul.w);
            *(uint4*)&Bh[q][lrow * BSTR + lh] = uh;
            *(uint4*)&Bl[q][lrow * BSTR + lh] = ul;
        }
        __syncthreads();
    }

#pragma unroll
    for (int i = 0; i < 2; i++) {
        const int r0 = bm + wm + i * 16 + g;
#pragma unroll
        for (int j = 0; j < 8; j++) {
            const int cc = coff + bn + wn + j * 8 + c4 * 2;
            *(float2*)(C + (size_t)r0 * ldc + cc)       = make_float2(acc[i][j][0], acc[i][j][1]);
            *(float2*)(C + (size_t)(r0 + 8) * ldc + cc) = make_float2(acc[i][j][2], acc[i][j][3]);
        }
    }
}

// ---------------------------------------------------------------------------
// RoPE (proven).
// ---------------------------------------------------------------------------
__global__ void rope_kernel(float* __restrict__ qkv, const int* __restrict__ pos_ids)
{
    const int s = blockIdx.x;
    const int d = threadIdx.x;
    const double invf = exp(-(double)d * (9.210340371976184 / 128.0));
    const double ang  = (double)pos_ids[s] * invf;
    const float c  = (float)cos(ang);
    const float si = (float)sin(ang);

    float* row = qkv + (size_t)s * QKVN;
#pragma unroll
    for (int head = 0; head < 12; head++) {
        const int base = head * 256;
        const float x0 = row[base + d];
        const float x1 = row[base + d + 128];
        row[base + d]       = x0 * c - x1 * si;
        row[base + d + 128] = x1 * c + x0 * si;
    }
}

// ---------------------------------------------------------------------------
// prep_split (proven): one-time K/V hi/lo split, V transposed.
// ---------------------------------------------------------------------------
__global__ void __launch_bounds__(256) prep_split(const float* __restrict__ qkv)
{
    __shared__ unsigned short sVh[32][260], sVl[32][260];

    const int kvh = blockIdx.y;
    const int kt  = blockIdx.x * 32;
    const int tid = threadIdx.x;
    const int r   = tid >> 3;
    const int cb  = (tid & 7) * 32;

    const float* krow = qkv + (size_t)(kt + r) * QKVN + NH * HD + kvh * HD + cb;
    const float* vrow = krow + NKV * HD;
    uint32_t* khp = gKh + ((size_t)kvh * S_LEN + kt + r) * 128 + cb / 2;
    uint32_t* klp = gKl + ((size_t)kvh * S_LEN + kt + r) * 128 + cb / 2;

#pragma unroll
    for (int i = 0; i < 8; i++) {
        float4 kv = *(const float4*)(krow + i * 4);
        uint32_t h0, l0, h1, l1;
        split2(kv.x, kv.y, h0, l0);
        split2(kv.z, kv.w, h1, l1);
        khp[i * 2] = h0; khp[i * 2 + 1] = h1;
        klp[i * 2] = l0; klp[i * 2 + 1] = l1;

        float4 vv = *(const float4*)(vrow + i * 4);
        uint32_t vh0, vl0, vh1, vl1;
        split2(vv.x, vv.y, vh0, vl0);
        split2(vv.z, vv.w, vh1, vl1);
        *(uint32_t*)&sVh[r][cb + i * 4]     = vh0;
        *(uint32_t*)&sVh[r][cb + i * 4 + 2] = vh1;
        *(uint32_t*)&sVl[r][cb + i * 4]     = vl0;
        *(uint32_t*)&sVl[r][cb + i * 4 + 2] = vl1;
    }
    __syncthreads();

    const int d = tid;
    uint32_t* vhp = gVh + ((size_t)kvh * HD + d) * (S_LEN / 2) + kt / 2;
    uint32_t* vlp = gVl + ((size_t)kvh * HD + d) * (S_LEN / 2) + kt / 2;
#pragma unroll
    for (int j = 0; j < 16; j++) {
        vhp[j] = (uint32_t)sVh[2 * j][d] | ((uint32_t)sVh[2 * j + 1][d] << 16);
        vlp[j] = (uint32_t)sVl[2 * j][d] | ((uint32_t)sVl[2 * j + 1][d] << 16);
    }
}

// ---------------------------------------------------------------------------
// Tensor-core attention v5: cp.async double-buffered staging (R11-proven) +
// FUSED softcap-exp softmax via raw MUFU PTX:
//   exp(50*tanh(s/50) - 50) == 2^(-144.2695.../(2^(s*0.0577078...) + 1))
//   -> ex2, rcp, ex2 (3 MUFU) + FMA, branchless; replaces libm tanhf+expf.
// ---------------------------------------------------------------------------
#define AQ_STR 132
#define AP_STR 20
#define QH_OFF 0
#define QL_OFF (64 * AQ_STR)
#define K_OFF  (2 * 64 * AQ_STR)
#define KBUF_STR (2 * 32 * AQ_STR)
#define V_OFF  (K_OFF + 2 * KBUF_STR)
#define VBUF_STR (2 * 256 * 16)
#define P_OFF  (V_OFF + 2 * VBUF_STR)
#define ATTN_SMEM_U32 (P_OFF + 2 * 64 * AP_STR)
#define ATTN_SMEM_BYTES (ATTN_SMEM_U32 * 4)

__device__ __forceinline__ float softcap_p(float s, int gq, int gk)
{
    // p = exp(50*tanh(s/50) - 50) = 2^(-144.2695.../(2^(s*2/(50 ln2)) + 1))
    float a = ex2_approx(s * 0.05770780163555852f);
    float p = ex2_approx(-144.26950408889634f * rcp_approx(a + 1.0f));
    bool ok = (gk <= gq) && ((gq - gk) < SWIN);
    return ok ? p : 0.f;
}

__global__ void __launch_bounds__(256) attn_mma5(
    const float* __restrict__ qkv, float* __restrict__ ao)
{
    extern __shared__ uint32_t smA[];
    uint32_t* Qh = smA + QH_OFF;
    uint32_t* Ql = smA + QL_OFF;
    uint32_t* Ph = smA + P_OFF;
    uint32_t* Pl = smA + P_OFF + 64 * AP_STR;
    __shared__ float LS[2][64];

    const uint32_t smem_u32 = (uint32_t)__cvta_generic_to_shared(smA);

    const int h   = blockIdx.y;
    const int q0  = blockIdx.x * 64;
    const int kvh = h >> 1;
    const int tid = threadIdx.x;
    const int warp = tid >> 5, lane = tid & 31;
    const int g = lane >> 2, c4 = lane & 3;
    const int wm  = (warp >> 1) * 16;
    const int wh  = warp & 1;

    const int kr  = tid >> 3;
    const int kc  = (tid & 7) * 4;
    const int vdg = tid >> 2;
    const int vgp = tid & 3;
    const uint32_t* skh_b = gKh + ((size_t)kvh * S_LEN + kr) * 128 + kc;
    const uint32_t* skl_b = gKl + ((size_t)kvh * S_LEN + kr) * 128 + kc;
    const uint32_t* svh_b = gVh + ((size_t)kvh * HD) * (S_LEN / 2) + vgp * 4;
    const uint32_t* svl_b = gVl + ((size_t)kvh * HD) * (S_LEN / 2) + vgp * 4;

    // ---- Load Q tile [64 x 256], pre-scaled, split into Qh/Ql ----
    {
        const int row = tid >> 2;
        const int cb  = (tid & 3) * 64;
        const float* qrow = qkv + (size_t)(q0 + row) * QKVN + h * HD + cb;
        uint32_t* qhp = Qh + row * AQ_STR + cb / 2;
        uint32_t* qlp = Ql + row * AQ_STR + cb / 2;
#pragma unroll
        for (int i = 0; i < 16; i++) {
            float4 v = *(const float4*)(qrow + i * 4);
            v.x *= SCALE_F; v.y *= SCALE_F; v.z *= SCALE_F; v.w *= SCALE_F;
            uint32_t h0, l0, h1, l1;
            split2(v.x, v.y, h0, l0);
            split2(v.z, v.w, h1, l1);
            qhp[i * 2] = h0; qhp[i * 2 + 1] = h1;
            qlp[i * 2] = l0; qlp[i * 2 + 1] = l1;
        }
    }

    float oacc[16][4];
#pragma unroll
    for (int nf = 0; nf < 16; nf++)
#pragma unroll
        for (int t = 0; t < 4; t++) oacc[nf][t] = 0.f;
    float lsum0 = 0.f, lsum1 = 0.f;

    int klo = q0 - (SWIN - 1);
    if (klo < 0) klo = 0;
    klo &= ~31;
    const int khi = q0 + 63;

    auto stage = [&](int kt_, int b) {
        const uint32_t kh_d = smem_u32 + (K_OFF + b * KBUF_STR + kr * AQ_STR + kc) * 4;
        const uint32_t kl_d = kh_d + (32 * AQ_STR) * 4;
        const uint32_t* skh = skh_b + (size_t)kt_ * 128;
        const uint32_t* skl = skl_b + (size_t)kt_ * 128;
#pragma unroll
        for (int i = 0; i < 4; i++) {
            cpa16(kh_d + i * 128, skh + i * 32);
            cpa16(kl_d + i * 128, skl + i * 32);
        }
        const uint32_t* svh = svh_b + (kt_ >> 1);
        const uint32_t* svl = svl_b + (kt_ >> 1);
#pragma unroll
        for (int pass = 0; pass < 4; pass++) {
            const int d = pass * 64 + vdg;
            const int idx = d * 16 + 4 * (vgp ^ ((d >> 1) & 3));
            const uint32_t vh_d = smem_u32 + (V_OFF + b * VBUF_STR + idx) * 4;
            const uint32_t vl_d = vh_d + (256 * 16) * 4;
            cpa16(vh_d, svh + (size_t)d * (S_LEN / 2));
            cpa16(vl_d, svl + (size_t)d * (S_LEN / 2));
        }
        asm volatile("cp.async.commit_group;\n" ::: "memory");
    };

    stage(klo, 0);

    int ti = 0;
    for (int kt = klo; kt <= khi; kt += 32, ti++) {
        __syncthreads();
        const bool more = (kt + 32 <= khi);
        if (more) {
            stage(kt + 32, (ti + 1) & 1);
            asm volatile("cp.async.wait_group 1;\n" ::: "memory");
        } else {
            asm volatile("cp.async.wait_group 0;\n" ::: "memory");
        }
        __syncthreads();

        const uint32_t* Kh = smA + K_OFF + (ti & 1) * KBUF_STR;
        const uint32_t* Kl = Kh + 32 * AQ_STR;
        const uint32_t* Vh = smA + V_OFF + (ti & 1) * VBUF_STR;
        const uint32_t* Vl = Vh + 256 * 16;

        // ---- S = Q K^T ----
        float sacc[2][4];
#pragma unroll
        for (int f = 0; f < 2; f++)
#pragma unroll
            for (int t = 0; t < 4; t++) sacc[f][t] = 0.f;

#pragma unroll 4
        for (int ks = 0; ks < 16; ks++) {
            const int qa = (wm + g) * AQ_STR + ks * 8 + c4;
            uint32_t ah0 = Qh[qa], ah1 = Qh[qa + 8 * AQ_STR];
            uint32_t ah2 = Qh[qa + 4], ah3 = Qh[qa + 8 * AQ_STR + 4];
            uint32_t al0 = Ql[qa], al1 = Ql[qa + 8 * AQ_STR];
            uint32_t al2 = Ql[qa + 4], al3 = Ql[qa + 8 * AQ_STR + 4];
            const int kb = (wh * 16 + g) * AQ_STR + ks * 8 + c4;
#pragma unroll
            for (int f = 0; f < 2; f++) {
                const int kbf = kb + f * 8 * AQ_STR;
                uint32_t bh0 = Kh[kbf], bh1 = Kh[kbf + 4];
                uint32_t bl0 = Kl[kbf], bl1 = Kl[kbf + 4];
                mma_bf16(sacc[f], ah0, ah1, ah2, ah3, bh0, bh1);
                mma_bf16(sacc[f], ah0, ah1, ah2, ah3, bl0, bl1);
                mma_bf16(sacc[f], al0, al1, al2, al3, bh0, bh1);
            }
        }

        // ---- fused softcap-exp softmax + pack P ----
        {
            const int r0 = q0 + wm + g;
            const int kb0 = kt + wh * 16 + 2 * c4;
#pragma unroll
            for (int f = 0; f < 2; f++) {
                const int kk = kb0 + f * 8;
                float p00 = softcap_p(sacc[f][0], r0, kk);
                float p01 = softcap_p(sacc[f][1], r0, kk + 1);
                float p10 = softcap_p(sacc[f][2], r0 + 8, kk);
                float p11 = softcap_p(sacc[f][3], r0 + 8, kk + 1);
                lsum0 += p00 + p01;
                lsum1 += p10 + p11;
                uint32_t hi, lo;
                split2(p00, p01, hi, lo);
                Ph[(wm + g) * AP_STR + wh * 8 + f * 4 + c4] = hi;
                Pl[(wm + g) * AP_STR + wh * 8 + f * 4 + c4] = lo;
                split2(p10, p11, hi, lo);
                Ph[(wm + g + 8) * AP_STR + wh * 8 + f * 4 + c4] = hi;
                Pl[(wm + g + 8) * AP_STR + wh * 8 + f * 4 + c4] = lo;
            }
        }
        __syncthreads();

        // ---- O += P V ----
#pragma unroll
        for (int ks2 = 0; ks2 < 2; ks2++) {
            const int pa = (wm + g) * AP_STR + ks2 * 8 + c4;
            uint32_t pah0 = Ph[pa], pah1 = Ph[pa + 8 * AP_STR];
            uint32_t pah2 = Ph[pa + 4], pah3 = Ph[pa + 8 * AP_STR + 4];
            uint32_t pal0 = Pl[pa], pal1 = Pl[pa + 8 * AP_STR];
            uint32_t pal2 = Pl[pa + 4], pal3 = Pl[pa + 8 * AP_STR + 4];
#pragma unroll
            for (int nf = 0; nf < 16; nf++) {
                const int dn = wh * 128 + nf * 8 + g;
                const int vb = dn * 16;
                const int sw = (dn >> 1) & 3;
                const int i0 = vb + 4 * ((2 * ks2) ^ sw) + c4;
                const int i1 = vb + 4 * ((2 * ks2 + 1) ^ sw) + c4;
                uint32_t vh0 = Vh[i0], vh1 = Vh[i1];
                uint32_t vl0 = Vl[i0], vl1 = Vl[i1];
                mma_bf16(oacc[nf], pah0, pah1, pah2, pah3, vh0, vh1);
                mma_bf16(oacc[nf], pah0, pah1, pah2, pah3, vl0, vl1);
                mma_bf16(oacc[nf], pal0, pal1, pal2, pal3, vh0, vh1);
            }
        }
    }

    // ---- reduce row sums ----
    lsum0 += __shfl_xor_sync(0xffffffffu, lsum0, 1);
    lsum0 += __shfl_xor_sync(0xffffffffu, lsum0, 2);
    lsum1 += __shfl_xor_sync(0xffffffffu, lsum1, 1);
    lsum1 += __shfl_xor_sync(0xffffffffu, lsum1, 2);
    if (c4 == 0) {
        LS[wh][wm + g]     = lsum0;
        LS[wh][wm + g + 8] = lsum1;
    }
    __syncthreads();
    const float inv0 = 1.0f / (LS[0][wm + g] + LS[1][wm + g]);
    const float inv1 = 1.0f / (LS[0][wm + g + 8] + LS[1][wm + g + 8]);

    // ---- store O ----
    {
        float* r0p = ao + (size_t)(q0 + wm + g) * (NH * HD) + h * HD + wh * 128;
        float* r1p = ao + (size_t)(q0 + wm + g + 8) * (NH * HD) + h * HD + wh * 128;
#pragma unroll
        for (int nf = 0; nf < 16; nf++) {
            const int dc = nf * 8 + 2 * c4;
            *(float2*)(r0p + dc) = make_float2(oacc[nf][0] * inv0, oacc[nf][1] * inv0);
            *(float2*)(r1p + dc) = make_float2(oacc[nf][2] * inv1, oacc[nf][3] * inv1);
        }
    }
}

// ---------------------------------------------------------------------------
// Inputs: hidden f32 [1,4096,2304], mask (ignored — analytic), Wq [2048,2304],
// Wk [1024,2304], Wv [1024,2304], Wo [2304,2048], position_ids i32 [1,4096].
// ---------------------------------------------------------------------------
extern "C" void kernel_launch(void* const* d_in, const int* in_sizes, int n_in,
                              void* d_out, int out_size)
{
    const float* hidden = (const float*)d_in[0];
    const float* Wq     = (const float*)d_in[2];
    const float* Wk     = (const float*)d_in[3];
    const float* Wv     = (const float*)d_in[4];
    const float* Wo     = (const float*)d_in[5];
    const int*   pos    = (const int*)d_in[6];
    float*       out    = (float*)d_out;

    float *qkv, *ao;
    cudaGetSymbolAddress((void**)&qkv, g_qkv);
    cudaGetSymbolAddress((void**)&ao,  g_ao);

    cudaFuncSetAttribute(attn_mma5, cudaFuncAttributeMaxDynamicSharedMemorySize, ATTN_SMEM_BYTES);

    // QKV projections (proven)
    gemm_bf16s<<<dim3(16, 32), 256>>>(hidden, Wq, qkv, HIDDEN, HIDDEN, HIDDEN, QKVN, 0);
    gemm_bf16s<<<dim3(8, 32), 256>>>(hidden, Wk, qkv, HIDDEN, HIDDEN, HIDDEN, QKVN, 2048);
    gemm_bf16s<<<dim3(8, 32), 256>>>(hidden, Wv, qkv, HIDDEN, HIDDEN, HIDDEN, QKVN, 3072);

    // RoPE (proven)
    rope_kernel<<<S_LEN, 128>>>(qkv, pos);

    // One-time K/V hi/lo split into copy-ready layouts
    prep_split<<<dim3(S_LEN / 32, NKV), 256>>>(qkv);

    // Tensor-core attention: cp.async pipeline + fused softcap-exp (MUFU)
    attn_mma5<<<dim3(S_LEN / 64, NH), 256, ATTN_SMEM_BYTES>>>(qkv, ao);

    // Output projection (proven)
    gemm_bf16s<<<dim3(18, 32), 256>>>(ao, Wo, out, NH * HD, NH * HD, NH * HD, HIDDEN, 0);
}

// round 14
// speedup vs baseline: 1.7930x; 1.0146x over previous
#include <cuda_runtime.h>
#include <cuda_bf16.h>
#include <math.h>
#include <stdint.h>

// Problem constants
#define S_LEN   4096
#define HIDDEN  2304
#define NH      8
#define NKV     4
#define HD      256
#define QKVN    4096
#define SWIN    2048
#define SCALE_F 0.0625f
#define CAP_F   50.0f

// Scratch (device globals)
__device__ float g_qkv[(size_t)S_LEN * QKVN];
__device__ float g_ao[(size_t)S_LEN * (NH * HD)];
// Pre-split K/V (bf16 hi/lo):
//   gK*: [kvh][key 4096][dim-pair 128 u32]
//   gV*: [kvh][dim 256][key-pair 2048 u32]  (transposed)
__device__ uint32_t gKh[(size_t)NKV * S_LEN * 128];
__device__ uint32_t gKl[(size_t)NKV * S_LEN * 128];
__device__ uint32_t gVh[(size_t)NKV * HD * (S_LEN / 2)];
__device__ uint32_t gVl[(size_t)NKV * HD * (S_LEN / 2)];

// ---------------------------------------------------------------------------
// Shared helpers
// ---------------------------------------------------------------------------
__device__ __forceinline__ void mma_bf16(float* d,
    uint32_t a0, uint32_t a1, uint32_t a2, uint32_t a3, uint32_t b0, uint32_t b1)
{
    asm volatile(
        "mma.sync.aligned.m16n8k16.row.col.f32.bf16.bf16.f32 "
        "{%0,%1,%2,%3}, {%4,%5,%6,%7}, {%8,%9}, {%0,%1,%2,%3};\n"
        : "+f"(d[0]), "+f"(d[1]), "+f"(d[2]), "+f"(d[3])
        : "r"(a0), "r"(a1), "r"(a2), "r"(a3), "r"(b0), "r"(b1));
}

__device__ __forceinline__ void split2(float x, float y, uint32_t& hi, uint32_t& lo)
{
    __nv_bfloat16 hx = __float2bfloat16_rn(x);
    __nv_bfloat16 hy = __float2bfloat16_rn(y);
    __nv_bfloat16 lx = __float2bfloat16_rn(x - __bfloat162float(hx));
    __nv_bfloat16 ly = __float2bfloat16_rn(y - __bfloat162float(hy));
    __nv_bfloat162 h2 = __halves2bfloat162(hx, hy);
    __nv_bfloat162 l2 = __halves2bfloat162(lx, ly);
    hi = *(uint32_t*)&h2;
    lo = *(uint32_t*)&l2;
}

__device__ __forceinline__ void cpa16(uint32_t dst_smem, const uint32_t* src)
{
    asm volatile("cp.async.ca.shared.global [%0], [%1], 16;\n"
                 :: "r"(dst_smem), "l"(src));
}

__device__ __forceinline__ float ex2_approx(float x)
{
    float r;
    asm("ex2.approx.f32 %0, %1;" : "=f"(r) : "f"(x));
    return r;
}

__device__ __forceinline__ float rcp_approx(float x)
{
    float r;
    asm("rcp.approx.f32 %0, %1;" : "=f"(r) : "f"(x));
    return r;
}

__device__ __forceinline__ void ldsm4(uint32_t& r0, uint32_t& r1, uint32_t& r2,
                                      uint32_t& r3, uint32_t addr)
{
    asm volatile("ldmatrix.sync.aligned.m8n8.x4.shared.b16 {%0,%1,%2,%3}, [%4];"
                 : "=r"(r0), "=r"(r1), "=r"(r2), "=r"(r3) : "r"(addr));
}

// ---------------------------------------------------------------------------
// bf16 hi/lo split GEMM (R6/R7-proven)
// ---------------------------------------------------------------------------
#define BSTR 12
#define BBUF (128 * BSTR)

__global__ void __launch_bounds__(256) gemm_bf16s(
    const float* __restrict__ A, const float* __restrict__ B, float* __restrict__ C,
    int K, int lda, int ldb, int ldc, int coff)
{
    __shared__ uint32_t Ah[2][BBUF], Al[2][BBUF];
    __shared__ uint32_t Bh[2][BBUF], Bl[2][BBUF];

    const int tid  = threadIdx.x;
    const int warp = tid >> 5, lane = tid & 31;
    const int g    = lane >> 2, c4 = lane & 3;
    const int wm   = (warp >> 1) * 32, wn = (warp & 1) * 64;
    const int bm   = blockIdx.y * 128, bn = blockIdx.x * 128;

    const int lrow = tid >> 1;
    const int lh   = (tid & 1) * 4;

    const float* Abase = A + (size_t)(bm + lrow) * lda + lh * 2;
    const float* Bbase = B + (size_t)(bn + lrow) * ldb + lh * 2;

    float acc[2][8][4];
#pragma unroll
    for (int i = 0; i < 2; i++)
#pragma unroll
        for (int j = 0; j < 8; j++)
#pragma unroll
            for (int t = 0; t < 4; t++) acc[i][j][t] = 0.f;

    const int nc = K >> 4;
    float4 ra0, ra1, rb0, rb1;

    ra0 = *(const float4*)(Abase);
    ra1 = *(const float4*)(Abase + 4);
    rb0 = *(const float4*)(Bbase);
    rb1 = *(const float4*)(Bbase + 4);
    {
        uint4 uh, ul;
        split2(ra0.x, ra0.y, uh.x, ul.x); split2(ra0.z, ra0.w, uh.y, ul.y);
        split2(ra1.x, ra1.y, uh.z, ul.z); split2(ra1.z, ra1.w, uh.w, ul.w);
        *(uint4*)&Ah[0][lrow * BSTR + lh] = uh;
        *(uint4*)&Al[0][lrow * BSTR + lh] = ul;
        split2(rb0.x, rb0.y, uh.x, ul.x); split2(rb0.z, rb0.w, uh.y, ul.y);
        split2(rb1.x, rb1.y, uh.z, ul.z); split2(rb1.z, rb1.w, uh.w, ul.w);
        *(uint4*)&Bh[0][lrow * BSTR + lh] = uh;
        *(uint4*)&Bl[0][lrow * BSTR + lh] = ul;
    }
    __syncthreads();

    for (int ch = 0; ch < nc; ch++) {
        const int p = ch & 1;
        if (ch + 1 < nc) {
            const float* ap = Abase + (size_t)(ch + 1) * 16;
            const float* bp = Bbase + (size_t)(ch + 1) * 16;
            ra0 = *(const float4*)(ap);
            ra1 = *(const float4*)(ap + 4);
            rb0 = *(const float4*)(bp);
            rb1 = *(const float4*)(bp + 4);
        }

        uint32_t ah[2][4], al[2][4];
#pragma unroll
        for (int i = 0; i < 2; i++) {
            const int r = wm + i * 16 + g;
            ah[i][0] = Ah[p][r * BSTR + c4];       ah[i][1] = Ah[p][(r + 8) * BSTR + c4];
            ah[i][2] = Ah[p][r * BSTR + c4 + 4];   ah[i][3] = Ah[p][(r + 8) * BSTR + c4 + 4];
            al[i][0] = Al[p][r * BSTR + c4];       al[i][1] = Al[p][(r + 8) * BSTR + c4];
            al[i][2] = Al[p][r * BSTR + c4 + 4];   al[i][3] = Al[p][(r + 8) * BSTR + c4 + 4];
        }
#pragma unroll
        for (int j = 0; j < 8; j++) {
            const int n = wn + j * 8 + g;
            uint32_t bh0 = Bh[p][n * BSTR + c4], bh1 = Bh[p][n * BSTR + c4 + 4];
            uint32_t bl0 = Bl[p][n * BSTR + c4], bl1 = Bl[p][n * BSTR + c4 + 4];
#pragma unroll
            for (int i = 0; i < 2; i++) {
                mma_bf16(acc[i][j], ah[i][0], ah[i][1], ah[i][2], ah[i][3], bh0, bh1);
                mma_bf16(acc[i][j], ah[i][0], ah[i][1], ah[i][2], ah[i][3], bl0, bl1);
                mma_bf16(acc[i][j], al[i][0], al[i][1], al[i][2], al[i][3], bh0, bh1);
            }
        }

        if (ch + 1 < nc) {
            const int q = p ^ 1;
            uint4 uh, ul;
            split2(ra0.x, ra0.y, uh.x, ul.x); split2(ra0.z, ra0.w, uh.y, ul.y);
            split2(ra1.x, ra1.y, uh.z, ul.z); split2(ra1.z, ra1.w, uh.w, ul.w);
            *(uint4*)&Ah[q][lrow * BSTR + lh] = uh;
            *(uint4*)&Al[q][lrow * BSTR + lh] = ul;
            split2(rb0.x, rb0.y, uh.x, ul.x); split2(rb0.z, rb0.w, uh.y, ul.y);
            split2(rb1.x, rb1.y, uh.z, ul.z); split2(rb1.z, rb1.w, uh.w, ul.w);
            *(uint4*)&Bh[q][lrow * BSTR + lh] = uh;
            *(uint4*)&Bl[q][lrow * BSTR + lh] = ul;
        }
        __syncthreads();
    }

#pragma unroll
    for (int i = 0; i < 2; i++) {
        const int r0 = bm + wm + i * 16 + g;
#pragma unroll
        for (int j = 0; j < 8; j++) {
            const int cc = coff + bn + wn + j * 8 + c4 * 2;
            *(float2*)(C + (size_t)r0 * ldc + cc)       = make_float2(acc[i][j][0], acc[i][j][1]);
            *(float2*)(C + (size_t)(r0 + 8) * ldc + cc) = make_float2(acc[i][j][2], acc[i][j][3]);
        }
    }
}

// ---------------------------------------------------------------------------
// RoPE (proven).
// ---------------------------------------------------------------------------
__global__ void rope_kernel(float* __restrict__ qkv, const int* __restrict__ pos_ids)
{
    const int s = blockIdx.x;
    const int d = threadIdx.x;
    const double invf = exp(-(double)d * (9.210340371976184 / 128.0));
    const double ang  = (double)pos_ids[s] * invf;
    const float c  = (float)cos(ang);
    const float si = (float)sin(ang);

    float* row = qkv + (size_t)s * QKVN;
#pragma unroll
    for (int head = 0; head < 12; head++) {
        const int base = head * 256;
        const float x0 = row[base + d];
        const float x1 = row[base + d + 128];
        row[base + d]       = x0 * c - x1 * si;
        row[base + d + 128] = x1 * c + x0 * si;
    }
}

// ---------------------------------------------------------------------------
// prep_split (proven): one-time K/V hi/lo split, V transposed.
// ---------------------------------------------------------------------------
__global__ void __launch_bounds__(256) prep_split(const float* __restrict__ qkv)
{
    __shared__ unsigned short sVh[32][260], sVl[32][260];

    const int kvh = blockIdx.y;
    const int kt  = blockIdx.x * 32;
    const int tid = threadIdx.x;
    const int r   = tid >> 3;
    const int cb  = (tid & 7) * 32;

    const float* krow = qkv + (size_t)(kt + r) * QKVN + NH * HD + kvh * HD + cb;
    const float* vrow = krow + NKV * HD;
    uint32_t* khp = gKh + ((size_t)kvh * S_LEN + kt + r) * 128 + cb / 2;
    uint32_t* klp = gKl + ((size_t)kvh * S_LEN + kt + r) * 128 + cb / 2;

#pragma unroll
    for (int i = 0; i < 8; i++) {
        float4 kv = *(const float4*)(krow + i * 4);
        uint32_t h0, l0, h1, l1;
        split2(kv.x, kv.y, h0, l0);
        split2(kv.z, kv.w, h1, l1);
        khp[i * 2] = h0; khp[i * 2 + 1] = h1;
        klp[i * 2] = l0; klp[i * 2 + 1] = l1;

        float4 vv = *(const float4*)(vrow + i * 4);
        uint32_t vh0, vl0, vh1, vl1;
        split2(vv.x, vv.y, vh0, vl0);
        split2(vv.z, vv.w, vh1, vl1);
        *(uint32_t*)&sVh[r][cb + i * 4]     = vh0;
        *(uint32_t*)&sVh[r][cb + i * 4 + 2] = vh1;
        *(uint32_t*)&sVl[r][cb + i * 4]     = vl0;
        *(uint32_t*)&sVl[r][cb + i * 4 + 2] = vl1;
    }
    __syncthreads();

    const int d = tid;
    uint32_t* vhp = gVh + ((size_t)kvh * HD + d) * (S_LEN / 2) + kt / 2;
    uint32_t* vlp = gVl + ((size_t)kvh * HD + d) * (S_LEN / 2) + kt / 2;
#pragma unroll
    for (int j = 0; j < 16; j++) {
        vhp[j] = (uint32_t)sVh[2 * j][d] | ((uint32_t)sVh[2 * j + 1][d] << 16);
        vlp[j] = (uint32_t)sVl[2 * j][d] | ((uint32_t)sVl[2 * j + 1][d] << 16);
    }
}

// ---------------------------------------------------------------------------
// Tensor-core attention v6: R13 pipeline + ldmatrix fragment loads (4x fewer
// shared-mem instructions, bit-identical values) + S-phase even/odd ks
// accumulator split (2->4 HMMA dependency chains per warp).
// ---------------------------------------------------------------------------
#define AQ_STR 132
#define AP_STR 20
#define QH_OFF 0
#define QL_OFF (64 * AQ_STR)
#define K_OFF  (2 * 64 * AQ_STR)
#define KBUF_STR (2 * 32 * AQ_STR)
#define V_OFF  (K_OFF + 2 * KBUF_STR)
#define VBUF_STR (2 * 256 * 16)
#define P_OFF  (V_OFF + 2 * VBUF_STR)
#define ATTN_SMEM_U32 (P_OFF + 2 * 64 * AP_STR)
#define ATTN_SMEM_BYTES (ATTN_SMEM_U32 * 4)

__device__ __forceinline__ float softcap_p(float s, int gq, int gk)
{
    // p = exp(50*tanh(s/50) - 50) = 2^(-144.2695.../(2^(s*2/(50 ln2)) + 1))
    float a = ex2_approx(s * 0.05770780163555852f);
    float p = ex2_approx(-144.26950408889634f * rcp_approx(a + 1.0f));
    bool ok = (gk <= gq) && ((gq - gk) < SWIN);
    return ok ? p : 0.f;
}

__global__ void __launch_bounds__(256) attn_mma6(
    const float* __restrict__ qkv, float* __restrict__ ao)
{
    extern __shared__ uint32_t smA[];
    uint32_t* Qh = smA + QH_OFF;
    uint32_t* Ql = smA + QL_OFF;
    uint32_t* Ph = smA + P_OFF;
    uint32_t* Pl = smA + P_OFF + 64 * AP_STR;
    __shared__ float LS[2][64];

    const uint32_t smem_u32 = (uint32_t)__cvta_generic_to_shared(smA);

    const int h   = blockIdx.y;
    const int q0  = blockIdx.x * 64;
    const int kvh = h >> 1;
    const int tid = threadIdx.x;
    const int warp = tid >> 5, lane = tid & 31;
    const int g = lane >> 2, c4 = lane & 3;
    const int wm  = (warp >> 1) * 16;
    const int wh  = warp & 1;

    // ldmatrix per-lane decomposition
    const int lr = lane & 7;      // row within 8x8 matrix
    const int lm = lane >> 3;     // matrix id 0..3

    // cp.async staging indices
    const int kr  = tid >> 3;
    const int kc  = (tid & 7) * 4;
    const int vdg = tid >> 2;
    const int vgp = tid & 3;
    const uint32_t* skh_b = gKh + ((size_t)kvh * S_LEN + kr) * 128 + kc;
    const uint32_t* skl_b = gKl + ((size_t)kvh * S_LEN + kr) * 128 + kc;
    const uint32_t* svh_b = gVh + ((size_t)kvh * HD) * (S_LEN / 2) + vgp * 4;
    const uint32_t* svl_b = gVl + ((size_t)kvh * HD) * (S_LEN / 2) + vgp * 4;

    // ---- Load Q tile [64 x 256], pre-scaled, split into Qh/Ql ----
    {
        const int row = tid >> 2;
        const int cb  = (tid & 3) * 64;
        const float* qrow = qkv + (size_t)(q0 + row) * QKVN + h * HD + cb;
        uint32_t* qhp = Qh + row * AQ_STR + cb / 2;
        uint32_t* qlp = Ql + row * AQ_STR + cb / 2;
#pragma unroll
        for (int i = 0; i < 16; i++) {
            float4 v = *(const float4*)(qrow + i * 4);
            v.x *= SCALE_F; v.y *= SCALE_F; v.z *= SCALE_F; v.w *= SCALE_F;
            uint32_t h0, l0, h1, l1;
            split2(v.x, v.y, h0, l0);
            split2(v.z, v.w, h1, l1);
            qhp[i * 2] = h0; qhp[i * 2 + 1] = h1;
            qlp[i * 2] = l0; qlp[i * 2 + 1] = l1;
        }
    }

    // ldmatrix base addresses (byte addresses in shared space)
    // Q/P A-fragments: matrix m -> rows (wm + lr + (m&1)*8), col chunk (m>>1)*4
    const uint32_t qh_lb = smem_u32 + (QH_OFF + (wm + lr + (lm & 1) * 8) * AQ_STR + (lm >> 1) * 4) * 4;
    const uint32_t ql_lb = smem_u32 + (QL_OFF + (wm + lr + (lm & 1) * 8) * AQ_STR + (lm >> 1) * 4) * 4;
    const uint32_t ph_lb = smem_u32 + (P_OFF + (wm + lr + (lm & 1) * 8) * AP_STR + (lm >> 1) * 4) * 4;
    const uint32_t pl_lb = ph_lb + (64 * AP_STR) * 4;
    // K B-fragments: matrix m -> rows (wh*16 + (m>>1)*8 + lr), col chunk (m&1)*4
    const uint32_t k_lrow = (wh * 16 + (lm >> 1) * 8 + lr) * AQ_STR + (lm & 1) * 4;

    float oacc[16][4];
#pragma unroll
    for (int nf = 0; nf < 16; nf++)
#pragma unroll
        for (int t = 0; t < 4; t++) oacc[nf][t] = 0.f;
    float lsum0 = 0.f, lsum1 = 0.f;

    int klo = q0 - (SWIN - 1);
    if (klo < 0) klo = 0;
    klo &= ~31;
    const int khi = q0 + 63;

    auto stage = [&](int kt_, int b) {
        const uint32_t kh_d = smem_u32 + (K_OFF + b * KBUF_STR + kr * AQ_STR + kc) * 4;
        const uint32_t kl_d = kh_d + (32 * AQ_STR) * 4;
        const uint32_t* skh = skh_b + (size_t)kt_ * 128;
        const uint32_t* skl = skl_b + (size_t)kt_ * 128;
#pragma unroll
        for (int i = 0; i < 4; i++) {
            cpa16(kh_d + i * 128, skh + i * 32);
            cpa16(kl_d + i * 128, skl + i * 32);
        }
        const uint32_t* svh = svh_b + (kt_ >> 1);
        const uint32_t* svl = svl_b + (kt_ >> 1);
#pragma unroll
        for (int pass = 0; pass < 4; pass++) {
            const int d = pass * 64 + vdg;
            const int idx = d * 16 + 4 * (vgp ^ ((d >> 1) & 3));
            const uint32_t vh_d = smem_u32 + (V_OFF + b * VBUF_STR + idx) * 4;
            const uint32_t vl_d = vh_d + (256 * 16) * 4;
            cpa16(vh_d, svh + (size_t)d * (S_LEN / 2));
            cpa16(vl_d, svl + (size_t)d * (S_LEN / 2));
        }
        asm volatile("cp.async.commit_group;\n" ::: "memory");
    };

    stage(klo, 0);

    int ti = 0;
    for (int kt = klo; kt <= khi; kt += 32, ti++) {
        __syncthreads();
        const bool more = (kt + 32 <= khi);
        if (more) {
            stage(kt + 32, (ti + 1) & 1);
            asm volatile("cp.async.wait_group 1;\n" ::: "memory");
        } else {
            asm volatile("cp.async.wait_group 0;\n" ::: "memory");
        }
        __syncthreads();

        const uint32_t kh_lb = smem_u32 + (K_OFF + (ti & 1) * KBUF_STR + k_lrow) * 4;
        const uint32_t kl_lb = kh_lb + (32 * AQ_STR) * 4;
        const uint32_t vh_bb = smem_u32 + (V_OFF + (ti & 1) * VBUF_STR) * 4;
        const uint32_t vl_bb = vh_bb + (256 * 16) * 4;

        // ---- S = Q K^T (ldmatrix frags; even/odd ks accumulator split) ----
        float sacc[2][2][4];
#pragma unroll
        for (int e = 0; e < 2; e++)
#pragma unroll
            for (int f = 0; f < 2; f++)
#pragma unroll
                for (int t = 0; t < 4; t++) sacc[e][f][t] = 0.f;

#pragma unroll 4
        for (int ks = 0; ks < 16; ks++) {
            const uint32_t koff = (uint32_t)(ks * 8 * 4);
            uint32_t ah0, ah1, ah2, ah3, al0, al1, al2, al3;
            ldsm4(ah0, ah1, ah2, ah3, qh_lb + koff);
            ldsm4(al0, al1, al2, al3, ql_lb + koff);
            uint32_t bh00, bh10, bh01, bh11, bl00, bl10, bl01, bl11;
            ldsm4(bh00, bh10, bh01, bh11, kh_lb + koff);  // (f0:b0,b1, f1:b0,b1)
            ldsm4(bl00, bl10, bl01, bl11, kl_lb + koff);
            float* s0 = sacc[ks & 1][0];
            float* s1 = sacc[ks & 1][1];
            mma_bf16(s0, ah0, ah1, ah2, ah3, bh00, bh10);
            mma_bf16(s1, ah0, ah1, ah2, ah3, bh01, bh11);
            mma_bf16(s0, ah0, ah1, ah2, ah3, bl00, bl10);
            mma_bf16(s1, ah0, ah1, ah2, ah3, bl01, bl11);
            mma_bf16(s0, al0, al1, al2, al3, bh00, bh10);
            mma_bf16(s1, al0, al1, al2, al3, bh01, bh11);
        }
#pragma unroll
        for (int f = 0; f < 2; f++)
#pragma unroll
            for (int t = 0; t < 4; t++) sacc[0][f][t] += sacc[1][f][t];

        // ---- fused softcap-exp softmax + pack P ----
        {
            const int r0 = q0 + wm + g;
            const int kb0 = kt + wh * 16 + 2 * c4;
#pragma unroll
            for (int f = 0; f < 2; f++) {
                const int kk = kb0 + f * 8;
                float p00 = softcap_p(sacc[0][f][0], r0, kk);
                float p01 = softcap_p(sacc[0][f][1], r0, kk + 1);
                float p10 = softcap_p(sacc[0][f][2], r0 + 8, kk);
                float p11 = softcap_p(sacc[0][f][3], r0 + 8, kk + 1);
                lsum0 += p00 + p01;
                lsum1 += p10 + p11;
                uint32_t hi, lo;
                split2(p00, p01, hi, lo);
                Ph[(wm + g) * AP_STR + wh * 8 + f * 4 + c4] = hi;
                Pl[(wm + g) * AP_STR + wh * 8 + f * 4 + c4] = lo;
                split2(p10, p11, hi, lo);
                Ph[(wm + g + 8) * AP_STR + wh * 8 + f * 4 + c4] = hi;
                Pl[(wm + g + 8) * AP_STR + wh * 8 + f * 4 + c4] = lo;
            }
        }
        __syncthreads();

        // ---- O += P V (ldmatrix frags) ----
#pragma unroll
        for (int ks2 = 0; ks2 < 2; ks2++) {
            uint32_t pah0, pah1, pah2, pah3, pal0, pal1, pal2, pal3;
            ldsm4(pah0, pah1, pah2, pah3, ph_lb + (uint32_t)(ks2 * 8 * 4));
            ldsm4(pal0, pal1, pal2, pal3, pl_lb + (uint32_t)(ks2 * 8 * 4));
#pragma unroll
            for (int nfp = 0; nfp < 8; nfp++) {
                // V B-frags for nf = 2*nfp and nf+1:
                // matrix m -> dim row dn = wh*128 + (2*nfp + (m>>1))*8 + lr,
                //             chunk (2*ks2 + (m&1)) ^ ((dn>>1)&3)
                const int dn  = wh * 128 + (2 * nfp + (lm >> 1)) * 8 + lr;
                const int swl = (dn >> 1) & 3;
                const uint32_t voff =
                    (uint32_t)((dn * 16 + 4 * ((2 * ks2 + (lm & 1)) ^ swl)) * 4);
                uint32_t va0, va1, vb0, vb1, wa0, wa1, wb0, wb1;
                ldsm4(va0, va1, vb0, vb1, vh_bb + voff);   // (nf:b0,b1, nf+1:b0,b1)
                ldsm4(wa0, wa1, wb0, wb1, vl_bb + voff);
                float* o0 = oacc[2 * nfp];
                float* o1 = oacc[2 * nfp + 1];
                mma_bf16(o0, pah0, pah1, pah2, pah3, va0, va1);
                mma_bf16(o1, pah0, pah1, pah2, pah3, vb0, vb1);
                mma_bf16(o0, pah0, pah1, pah2, pah3, wa0, wa1);
                mma_bf16(o1, pah0, pah1, pah2, pah3, wb0, wb1);
                mma_bf16(o0, pal0, pal1, pal2, pal3, va0, va1);
                mma_bf16(o1, pal0, pal1, pal2, pal3, vb0, vb1);
            }
        }
    }

    // ---- reduce row sums ----
    lsum0 += __shfl_xor_sync(0xffffffffu, lsum0, 1);
    lsum0 += __shfl_xor_sync(0xffffffffu, lsum0, 2);
    lsum1 += __shfl_xor_sync(0xffffffffu, lsum1, 1);
    lsum1 += __shfl_xor_sync(0xffffffffu, lsum1, 2);
    if (c4 == 0) {
        LS[wh][wm + g]     = lsum0;
        LS[wh][wm + g + 8] = lsum1;
    }
    __syncthreads();
    const float inv0 = 1.0f / (LS[0][wm + g] + LS[1][wm + g]);
    const float inv1 = 1.0f / (LS[0][wm + g + 8] + LS[1][wm + g + 8]);

    // ---- store O ----
    {
        float* r0p = ao + (size_t)(q0 + wm + g) * (NH * HD) + h * HD + wh * 128;
        float* r1p = ao + (size_t)(q0 + wm + g + 8) * (NH * HD) + h * HD + wh * 128;
#pragma unroll
        for (int nf = 0; nf < 16; nf++) {
            const int dc = nf * 8 + 2 * c4;
            *(float2*)(r0p + dc) = make_float2(oacc[nf][0] * inv0, oacc[nf][1] * inv0);
            *(float2*)(r1p + dc) = make_float2(oacc[nf][2] * inv1, oacc[nf][3] * inv1);
        }
    }
}

// ---------------------------------------------------------------------------
// Inputs: hidden f32 [1,4096,2304], mask (ignored — analytic), Wq [2048,2304],
// Wk [1024,2304], Wv [1024,2304], Wo [2304,2048], position_ids i32 [1,4096].
// ---------------------------------------------------------------------------
extern "C" void kernel_launch(void* const* d_in, const int* in_sizes, int n_in,
                              void* d_out, int out_size)
{
    const float* hidden = (const float*)d_in[0];
    const float* Wq     = (const float*)d_in[2];
    const float* Wk     = (const float*)d_in[3];
    const float* Wv     = (const float*)d_in[4];
    const float* Wo     = (const float*)d_in[5];
    const int*   pos    = (const int*)d_in[6];
    float*       out    = (float*)d_out;

    float *qkv, *ao;
    cudaGetSymbolAddress((void**)&qkv, g_qkv);
    cudaGetSymbolAddress((void**)&ao,  g_ao);

    cudaFuncSetAttribute(attn_mma6, cudaFuncAttributeMaxDynamicSharedMemorySize, ATTN_SMEM_BYTES);

    // QKV projections (proven)
    gemm_bf16s<<<dim3(16, 32), 256>>>(hidden, Wq, qkv, HIDDEN, HIDDEN, HIDDEN, QKVN, 0);
    gemm_bf16s<<<dim3(8, 32), 256>>>(hidden, Wk, qkv, HIDDEN, HIDDEN, HIDDEN, QKVN, 2048);
    gemm_bf16s<<<dim3(8, 32), 256>>>(hidden, Wv, qkv, HIDDEN, HIDDEN, HIDDEN, QKVN, 3072);

    // RoPE (proven)
    rope_kernel<<<S_LEN, 128>>>(qkv, pos);

    // One-time K/V hi/lo split into copy-ready layouts
    prep_split<<<dim3(S_LEN / 32, NKV), 256>>>(qkv);

    // Tensor-core attention: cp.async pipeline + ldmatrix + ILP split
    attn_mma6<<<dim3(S_LEN / 64, NH), 256, ATTN_SMEM_BYTES>>>(qkv, ao);

    // Output projection (proven)
    gemm_bf16s<<<dim3(18, 32), 256>>>(ao, Wo, out, NH * HD, NH * HD, NH * HD, HIDDEN, 0);
}

// round 15
// speedup vs baseline: 1.7992x; 1.0035x over previous
#include <cuda_runtime.h>
#include <cuda_bf16.h>
#include <math.h>
#include <stdint.h>

// Problem constants
#define S_LEN   4096
#define HIDDEN  2304
#define NH      8
#define NKV     4
#define HD      256
#define QKVN    4096
#define SWIN    2048
#define SCALE_F 0.0625f
#define CAP_F   50.0f

// Scratch (device globals)
__device__ float g_qkv[(size_t)S_LEN * QKVN];
__device__ float g_ao[(size_t)S_LEN * (NH * HD)];
// Pre-split K/V (bf16 hi/lo):
//   gK*: [kvh][key 4096][dim-pair 128 u32]
//   gV*: [kvh][dim 256][key-pair 2048 u32]  (transposed)
__device__ uint32_t gKh[(size_t)NKV * S_LEN * 128];
__device__ uint32_t gKl[(size_t)NKV * S_LEN * 128];
__device__ uint32_t gVh[(size_t)NKV * HD * (S_LEN / 2)];
__device__ uint32_t gVl[(size_t)NKV * HD * (S_LEN / 2)];

// ---------------------------------------------------------------------------
// Shared helpers
// ---------------------------------------------------------------------------
__device__ __forceinline__ void mma_bf16(float* d,
    uint32_t a0, uint32_t a1, uint32_t a2, uint32_t a3, uint32_t b0, uint32_t b1)
{
    asm volatile(
        "mma.sync.aligned.m16n8k16.row.col.f32.bf16.bf16.f32 "
        "{%0,%1,%2,%3}, {%4,%5,%6,%7}, {%8,%9}, {%0,%1,%2,%3};\n"
        : "+f"(d[0]), "+f"(d[1]), "+f"(d[2]), "+f"(d[3])
        : "r"(a0), "r"(a1), "r"(a2), "r"(a3), "r"(b0), "r"(b1));
}

__device__ __forceinline__ void split2(float x, float y, uint32_t& hi, uint32_t& lo)
{
    __nv_bfloat16 hx = __float2bfloat16_rn(x);
    __nv_bfloat16 hy = __float2bfloat16_rn(y);
    __nv_bfloat16 lx = __float2bfloat16_rn(x - __bfloat162float(hx));
    __nv_bfloat16 ly = __float2bfloat16_rn(y - __bfloat162float(hy));
    __nv_bfloat162 h2 = __halves2bfloat162(hx, hy);
    __nv_bfloat162 l2 = __halves2bfloat162(lx, ly);
    hi = *(uint32_t*)&h2;
    lo = *(uint32_t*)&l2;
}

__device__ __forceinline__ void cpa16(uint32_t dst_smem, const uint32_t* src)
{
    asm volatile("cp.async.ca.shared.global [%0], [%1], 16;\n"
                 :: "r"(dst_smem), "l"(src));
}

__device__ __forceinline__ float ex2_approx(float x)
{
    float r;
    asm("ex2.approx.f32 %0, %1;" : "=f"(r) : "f"(x));
    return r;
}

__device__ __forceinline__ float rcp_approx(float x)
{
    float r;
    asm("rcp.approx.f32 %0, %1;" : "=f"(r) : "f"(x));
    return r;
}

__device__ __forceinline__ void ldsm4(uint32_t& r0, uint32_t& r1, uint32_t& r2,
                                      uint32_t& r3, uint32_t addr)
{
    asm volatile("ldmatrix.sync.aligned.m8n8.x4.shared.b16 {%0,%1,%2,%3}, [%4];"
                 : "=r"(r0), "=r"(r1), "=r"(r2), "=r"(r3) : "r"(addr));
}

// ---------------------------------------------------------------------------
// bf16 hi/lo split GEMM (R6/R7-proven)
// ---------------------------------------------------------------------------
#define BSTR 12
#define BBUF (128 * BSTR)

__global__ void __launch_bounds__(256) gemm_bf16s(
    const float* __restrict__ A, const float* __restrict__ B, float* __restrict__ C,
    int K, int lda, int ldb, int ldc, int coff)
{
    __shared__ uint32_t Ah[2][BBUF], Al[2][BBUF];
    __shared__ uint32_t Bh[2][BBUF], Bl[2][BBUF];

    const int tid  = threadIdx.x;
    const int warp = tid >> 5, lane = tid & 31;
    const int g    = lane >> 2, c4 = lane & 3;
    const int wm   = (warp >> 1) * 32, wn = (warp & 1) * 64;
    const int bm   = blockIdx.y * 128, bn = blockIdx.x * 128;

    const int lrow = tid >> 1;
    const int lh   = (tid & 1) * 4;

    const float* Abase = A + (size_t)(bm + lrow) * lda + lh * 2;
    const float* Bbase = B + (size_t)(bn + lrow) * ldb + lh * 2;

    float acc[2][8][4];
#pragma unroll
    for (int i = 0; i < 2; i++)
#pragma unroll
        for (int j = 0; j < 8; j++)
#pragma unroll
            for (int t = 0; t < 4; t++) acc[i][j][t] = 0.f;

    const int nc = K >> 4;
    float4 ra0, ra1, rb0, rb1;

    ra0 = *(const float4*)(Abase);
    ra1 = *(const float4*)(Abase + 4);
    rb0 = *(const float4*)(Bbase);
    rb1 = *(const float4*)(Bbase + 4);
    {
        uint4 uh, ul;
        split2(ra0.x, ra0.y, uh.x, ul.x); split2(ra0.z, ra0.w, uh.y, ul.y);
        split2(ra1.x, ra1.y, uh.z, ul.z); split2(ra1.z, ra1.w, uh.w, ul.w);
        *(uint4*)&Ah[0][lrow * BSTR + lh] = uh;
        *(uint4*)&Al[0][lrow * BSTR + lh] = ul;
        split2(rb0.x, rb0.y, uh.x, ul.x); split2(rb0.z, rb0.w, uh.y, ul.y);
        split2(rb1.x, rb1.y, uh.z, ul.z); split2(rb1.z, rb1.w, uh.w, ul.w);
        *(uint4*)&Bh[0][lrow * BSTR + lh] = uh;
        *(uint4*)&Bl[0][lrow * BSTR + lh] = ul;
    }
    __syncthreads();

    for (int ch = 0; ch < nc; ch++) {
        const int p = ch & 1;
        if (ch + 1 < nc) {
            const float* ap = Abase + (size_t)(ch + 1) * 16;
            const float* bp = Bbase + (size_t)(ch + 1) * 16;
            ra0 = *(const float4*)(ap);
            ra1 = *(const float4*)(ap + 4);
            rb0 = *(const float4*)(bp);
            rb1 = *(const float4*)(bp + 4);
        }

        uint32_t ah[2][4], al[2][4];
#pragma unroll
        for (int i = 0; i < 2; i++) {
            const int r = wm + i * 16 + g;
            ah[i][0] = Ah[p][r * BSTR + c4];       ah[i][1] = Ah[p][(r + 8) * BSTR + c4];
            ah[i][2] = Ah[p][r * BSTR + c4 + 4];   ah[i][3] = Ah[p][(r + 8) * BSTR + c4 + 4];
            al[i][0] = Al[p][r * BSTR + c4];       al[i][1] = Al[p][(r + 8) * BSTR + c4];
            al[i][2] = Al[p][r * BSTR + c4 + 4];   al[i][3] = Al[p][(r + 8) * BSTR + c4 + 4];
        }
#pragma unroll
        for (int j = 0; j < 8; j++) {
            const int n = wn + j * 8 + g;
            uint32_t bh0 = Bh[p][n * BSTR + c4], bh1 = Bh[p][n * BSTR + c4 + 4];
            uint32_t bl0 = Bl[p][n * BSTR + c4], bl1 = Bl[p][n * BSTR + c4 + 4];
#pragma unroll
            for (int i = 0; i < 2; i++) {
                mma_bf16(acc[i][j], ah[i][0], ah[i][1], ah[i][2], ah[i][3], bh0, bh1);
                mma_bf16(acc[i][j], ah[i][0], ah[i][1], ah[i][2], ah[i][3], bl0, bl1);
                mma_bf16(acc[i][j], al[i][0], al[i][1], al[i][2], al[i][3], bh0, bh1);
            }
        }

        if (ch + 1 < nc) {
            const int q = p ^ 1;
            uint4 uh, ul;
            split2(ra0.x, ra0.y, uh.x, ul.x); split2(ra0.z, ra0.w, uh.y, ul.y);
            split2(ra1.x, ra1.y, uh.z, ul.z); split2(ra1.z, ra1.w, uh.w, ul.w);
            *(uint4*)&Ah[q][lrow * BSTR + lh] = uh;
            *(uint4*)&Al[q][lrow * BSTR + lh] = ul;
            split2(rb0.x, rb0.y, uh.x, ul.x); split2(rb0.z, rb0.w, uh.y, ul.y);
            split2(rb1.x, rb1.y, uh.z, ul.z); split2(rb1.z, rb1.w, uh.w, ul.w);
            *(uint4*)&Bh[q][lrow * BSTR + lh] = uh;
            *(uint4*)&Bl[q][lrow * BSTR + lh] = ul;
        }
        __syncthreads();
    }

#pragma unroll
    for (int i = 0; i < 2; i++) {
        const int r0 = bm + wm + i * 16 + g;
#pragma unroll
        for (int j = 0; j < 8; j++) {
            const int cc = coff + bn + wn + j * 8 + c4 * 2;
            *(float2*)(C + (size_t)r0 * ldc + cc)       = make_float2(acc[i][j][0], acc[i][j][1]);
            *(float2*)(C + (size_t)(r0 + 8) * ldc + cc) = make_float2(acc[i][j][2], acc[i][j][3]);
        }
    }
}

// ---------------------------------------------------------------------------
// RoPE (proven).
// ---------------------------------------------------------------------------
__global__ void rope_kernel(float* __restrict__ qkv, const int* __restrict__ pos_ids)
{
    const int s = blockIdx.x;
    const int d = threadIdx.x;
    const double invf = exp(-(double)d * (9.210340371976184 / 128.0));
    const double ang  = (double)pos_ids[s] * invf;
    const float c  = (float)cos(ang);
    const float si = (float)sin(ang);

    float* row = qkv + (size_t)s * QKVN;
#pragma unroll
    for (int head = 0; head < 12; head++) {
        const int base = head * 256;
        const float x0 = row[base + d];
        const float x1 = row[base + d + 128];
        row[base + d]       = x0 * c - x1 * si;
        row[base + d + 128] = x1 * c + x0 * si;
    }
}

// ---------------------------------------------------------------------------
// prep_split (proven): one-time K/V hi/lo split, V transposed.
// ---------------------------------------------------------------------------
__global__ void __launch_bounds__(256) prep_split(const float* __restrict__ qkv)
{
    __shared__ unsigned short sVh[32][260], sVl[32][260];

    const int kvh = blockIdx.y;
    const int kt  = blockIdx.x * 32;
    const int tid = threadIdx.x;
    const int r   = tid >> 3;
    const int cb  = (tid & 7) * 32;

    const float* krow = qkv + (size_t)(kt + r) * QKVN + NH * HD + kvh * HD + cb;
    const float* vrow = krow + NKV * HD;
    uint32_t* khp = gKh + ((size_t)kvh * S_LEN + kt + r) * 128 + cb / 2;
    uint32_t* klp = gKl + ((size_t)kvh * S_LEN + kt + r) * 128 + cb / 2;

#pragma unroll
    for (int i = 0; i < 8; i++) {
        float4 kv = *(const float4*)(krow + i * 4);
        uint32_t h0, l0, h1, l1;
        split2(kv.x, kv.y, h0, l0);
        split2(kv.z, kv.w, h1, l1);
        khp[i * 2] = h0; khp[i * 2 + 1] = h1;
        klp[i * 2] = l0; klp[i * 2 + 1] = l1;

        float4 vv = *(const float4*)(vrow + i * 4);
        uint32_t vh0, vl0, vh1, vl1;
        split2(vv.x, vv.y, vh0, vl0);
        split2(vv.z, vv.w, vh1, vl1);
        *(uint32_t*)&sVh[r][cb + i * 4]     = vh0;
        *(uint32_t*)&sVh[r][cb + i * 4 + 2] = vh1;
        *(uint32_t*)&sVl[r][cb + i * 4]     = vl0;
        *(uint32_t*)&sVl[r][cb + i * 4 + 2] = vl1;
    }
    __syncthreads();

    const int d = tid;
    uint32_t* vhp = gVh + ((size_t)kvh * HD + d) * (S_LEN / 2) + kt / 2;
    uint32_t* vlp = gVl + ((size_t)kvh * HD + d) * (S_LEN / 2) + kt / 2;
#pragma unroll
    for (int j = 0; j < 16; j++) {
        vhp[j] = (uint32_t)sVh[2 * j][d] | ((uint32_t)sVh[2 * j + 1][d] << 16);
        vlp[j] = (uint32_t)sVl[2 * j][d] | ((uint32_t)sVl[2 * j + 1][d] << 16);
    }
}

// ---------------------------------------------------------------------------
// Tensor-core attention v7: v6 (ldmatrix + cp.async pipeline + fused softmax)
//  + REVERSED CTA work order (heaviest sliding-window CTAs launch first ->
//    no heavy tail in the last wave; 512 CTAs over 152 SMs, work 2..66 tiles)
//  + pair-scoped named barrier for the P-write -> PV-read dependency
//    (only the two warps sharing wm need it; was a full-CTA syncthreads)
// Math bit-identical to R14 (rel_err must reproduce exactly).
// ---------------------------------------------------------------------------
#define AQ_STR 132
#define AP_STR 20
#define QH_OFF 0
#define QL_OFF (64 * AQ_STR)
#define K_OFF  (2 * 64 * AQ_STR)
#define KBUF_STR (2 * 32 * AQ_STR)
#define V_OFF  (K_OFF + 2 * KBUF_STR)
#define VBUF_STR (2 * 256 * 16)
#define P_OFF  (V_OFF + 2 * VBUF_STR)
#define ATTN_SMEM_U32 (P_OFF + 2 * 64 * AP_STR)
#define ATTN_SMEM_BYTES (ATTN_SMEM_U32 * 4)

__device__ __forceinline__ float softcap_p(float s, int gq, int gk)
{
    float a = ex2_approx(s * 0.05770780163555852f);
    float p = ex2_approx(-144.26950408889634f * rcp_approx(a + 1.0f));
    bool ok = (gk <= gq) && ((gq - gk) < SWIN);
    return ok ? p : 0.f;
}

__global__ void __launch_bounds__(256) attn_mma7(
    const float* __restrict__ qkv, float* __restrict__ ao)
{
    extern __shared__ uint32_t smA[];
    uint32_t* Qh = smA + QH_OFF;
    uint32_t* Ql = smA + QL_OFF;
    uint32_t* Ph = smA + P_OFF;
    uint32_t* Pl = smA + P_OFF + 64 * AP_STR;
    __shared__ float LS[2][64];

    const uint32_t smem_u32 = (uint32_t)__cvta_generic_to_shared(smA);

    const int h   = blockIdx.y;
    // REVERSED work order: heavy windows (large q0) first
    const int q0  = ((int)gridDim.x - 1 - (int)blockIdx.x) * 64;
    const int kvh = h >> 1;
    const int tid = threadIdx.x;
    const int warp = tid >> 5, lane = tid & 31;
    const int g = lane >> 2, c4 = lane & 3;
    const int wm  = (warp >> 1) * 16;
    const int wh  = warp & 1;
    const int pair_bar = 1 + (warp >> 1);   // named barrier id per wm-pair

    const int lr = lane & 7;
    const int lm = lane >> 3;

    const int kr  = tid >> 3;
    const int kc  = (tid & 7) * 4;
    const int vdg = tid >> 2;
    const int vgp = tid & 3;
    const uint32_t* skh_b = gKh + ((size_t)kvh * S_LEN + kr) * 128 + kc;
    const uint32_t* skl_b = gKl + ((size_t)kvh * S_LEN + kr) * 128 + kc;
    const uint32_t* svh_b = gVh + ((size_t)kvh * HD) * (S_LEN / 2) + vgp * 4;
    const uint32_t* svl_b = gVl + ((size_t)kvh * HD) * (S_LEN / 2) + vgp * 4;

    // ---- Load Q tile [64 x 256], pre-scaled, split into Qh/Ql ----
    {
        const int row = tid >> 2;
        const int cb  = (tid & 3) * 64;
        const float* qrow = qkv + (size_t)(q0 + row) * QKVN + h * HD + cb;
        uint32_t* qhp = Qh + row * AQ_STR + cb / 2;
        uint32_t* qlp = Ql + row * AQ_STR + cb / 2;
#pragma unroll
        for (int i = 0; i < 16; i++) {
            float4 v = *(const float4*)(qrow + i * 4);
            v.x *= SCALE_F; v.y *= SCALE_F; v.z *= SCALE_F; v.w *= SCALE_F;
            uint32_t h0, l0, h1, l1;
            split2(v.x, v.y, h0, l0);
            split2(v.z, v.w, h1, l1);
            qhp[i * 2] = h0; qhp[i * 2 + 1] = h1;
            qlp[i * 2] = l0; qlp[i * 2 + 1] = l1;
        }
    }

    const uint32_t qh_lb = smem_u32 + (QH_OFF + (wm + lr + (lm & 1) * 8) * AQ_STR + (lm >> 1) * 4) * 4;
    const uint32_t ql_lb = smem_u32 + (QL_OFF + (wm + lr + (lm & 1) * 8) * AQ_STR + (lm >> 1) * 4) * 4;
    const uint32_t ph_lb = smem_u32 + (P_OFF + (wm + lr + (lm & 1) * 8) * AP_STR + (lm >> 1) * 4) * 4;
    const uint32_t pl_lb = ph_lb + (64 * AP_STR) * 4;
    const uint32_t k_lrow = (wh * 16 + (lm >> 1) * 8 + lr) * AQ_STR + (lm & 1) * 4;

    float oacc[16][4];
#pragma unroll
    for (int nf = 0; nf < 16; nf++)
#pragma unroll
        for (int t = 0; t < 4; t++) oacc[nf][t] = 0.f;
    float lsum0 = 0.f, lsum1 = 0.f;

    int klo = q0 - (SWIN - 1);
    if (klo < 0) klo = 0;
    klo &= ~31;
    const int khi = q0 + 63;

    auto stage = [&](int kt_, int b) {
        const uint32_t kh_d = smem_u32 + (K_OFF + b * KBUF_STR + kr * AQ_STR + kc) * 4;
        const uint32_t kl_d = kh_d + (32 * AQ_STR) * 4;
        const uint32_t* skh = skh_b + (size_t)kt_ * 128;
        const uint32_t* skl = skl_b + (size_t)kt_ * 128;
#pragma unroll
        for (int i = 0; i < 4; i++) {
            cpa16(kh_d + i * 128, skh + i * 32);
            cpa16(kl_d + i * 128, skl + i * 32);
        }
        const uint32_t* svh = svh_b + (kt_ >> 1);
        const uint32_t* svl = svl_b + (kt_ >> 1);
#pragma unroll
        for (int pass = 0; pass < 4; pass++) {
            const int d = pass * 64 + vdg;
            const int idx = d * 16 + 4 * (vgp ^ ((d >> 1) & 3));
            const uint32_t vh_d = smem_u32 + (V_OFF + b * VBUF_STR + idx) * 4;
            const uint32_t vl_d = vh_d + (256 * 16) * 4;
            cpa16(vh_d, svh + (size_t)d * (S_LEN / 2));
            cpa16(vl_d, svl + (size_t)d * (S_LEN / 2));
        }
        asm volatile("cp.async.commit_group;\n" ::: "memory");
    };

    stage(klo, 0);

    int ti = 0;
    for (int kt = klo; kt <= khi; kt += 32, ti++) {
        __syncthreads();
        const bool more = (kt + 32 <= khi);
        if (more) {
            stage(kt + 32, (ti + 1) & 1);
            asm volatile("cp.async.wait_group 1;\n" ::: "memory");
        } else {
            asm volatile("cp.async.wait_group 0;\n" ::: "memory");
        }
        __syncthreads();

        const uint32_t kh_lb = smem_u32 + (K_OFF + (ti & 1) * KBUF_STR + k_lrow) * 4;
        const uint32_t kl_lb = kh_lb + (32 * AQ_STR) * 4;
        const uint32_t vh_bb = smem_u32 + (V_OFF + (ti & 1) * VBUF_STR) * 4;
        const uint32_t vl_bb = vh_bb + (256 * 16) * 4;

        // ---- S = Q K^T (ldmatrix frags; even/odd ks accumulator split) ----
        float sacc[2][2][4];
#pragma unroll
        for (int e = 0; e < 2; e++)
#pragma unroll
            for (int f = 0; f < 2; f++)
#pragma unroll
                for (int t = 0; t < 4; t++) sacc[e][f][t] = 0.f;

#pragma unroll 4
        for (int ks = 0; ks < 16; ks++) {
            const uint32_t koff = (uint32_t)(ks * 8 * 4);
            uint32_t ah0, ah1, ah2, ah3, al0, al1, al2, al3;
            ldsm4(ah0, ah1, ah2, ah3, qh_lb + koff);
            ldsm4(al0, al1, al2, al3, ql_lb + koff);
            uint32_t bh00, bh10, bh01, bh11, bl00, bl10, bl01, bl11;
            ldsm4(bh00, bh10, bh01, bh11, kh_lb + koff);
            ldsm4(bl00, bl10, bl01, bl11, kl_lb + koff);
            float* s0 = sacc[ks & 1][0];
            float* s1 = sacc[ks & 1][1];
            mma_bf16(s0, ah0, ah1, ah2, ah3, bh00, bh10);
            mma_bf16(s1, ah0, ah1, ah2, ah3, bh01, bh11);
            mma_bf16(s0, ah0, ah1, ah2, ah3, bl00, bl10);
            mma_bf16(s1, ah0, ah1, ah2, ah3, bl01, bl11);
            mma_bf16(s0, al0, al1, al2, al3, bh00, bh10);
            mma_bf16(s1, al0, al1, al2, al3, bh01, bh11);
        }
#pragma unroll
        for (int f = 0; f < 2; f++)
#pragma unroll
            for (int t = 0; t < 4; t++) sacc[0][f][t] += sacc[1][f][t];

        // ---- fused softcap-exp softmax + pack P ----
        {
            const int r0 = q0 + wm + g;
            const int kb0 = kt + wh * 16 + 2 * c4;
#pragma unroll
            for (int f = 0; f < 2; f++) {
                const int kk = kb0 + f * 8;
                float p00 = softcap_p(sacc[0][f][0], r0, kk);
                float p01 = softcap_p(sacc[0][f][1], r0, kk + 1);
                float p10 = softcap_p(sacc[0][f][2], r0 + 8, kk);
                float p11 = softcap_p(sacc[0][f][3], r0 + 8, kk + 1);
                lsum0 += p00 + p01;
                lsum1 += p10 + p11;
                uint32_t hi, lo;
                split2(p00, p01, hi, lo);
                Ph[(wm + g) * AP_STR + wh * 8 + f * 4 + c4] = hi;
                Pl[(wm + g) * AP_STR + wh * 8 + f * 4 + c4] = lo;
                split2(p10, p11, hi, lo);
                Ph[(wm + g + 8) * AP_STR + wh * 8 + f * 4 + c4] = hi;
                Pl[(wm + g + 8) * AP_STR + wh * 8 + f * 4 + c4] = lo;
            }
        }
        // pair-scoped barrier: only the two warps sharing wm exchange P
        asm volatile("bar.sync %0, 64;" :: "r"(pair_bar) : "memory");

        // ---- O += P V (ldmatrix frags) ----
#pragma unroll
        for (int ks2 = 0; ks2 < 2; ks2++) {
            uint32_t pah0, pah1, pah2, pah3, pal0, pal1, pal2, pal3;
            ldsm4(pah0, pah1, pah2, pah3, ph_lb + (uint32_t)(ks2 * 8 * 4));
            ldsm4(pal0, pal1, pal2, pal3, pl_lb + (uint32_t)(ks2 * 8 * 4));
#pragma unroll
            for (int nfp = 0; nfp < 8; nfp++) {
                const int dn  = wh * 128 + (2 * nfp + (lm >> 1)) * 8 + lr;
                const int swl = (dn >> 1) & 3;
                const uint32_t voff =
                    (uint32_t)((dn * 16 + 4 * ((2 * ks2 + (lm & 1)) ^ swl)) * 4);
                uint32_t va0, va1, vb0, vb1, wa0, wa1, wb0, wb1;
                ldsm4(va0, va1, vb0, vb1, vh_bb + voff);
                ldsm4(wa0, wa1, wb0, wb1, vl_bb + voff);
                float* o0 = oacc[2 * nfp];
                float* o1 = oacc[2 * nfp + 1];
                mma_bf16(o0, pah0, pah1, pah2, pah3, va0, va1);
                mma_bf16(o1, pah0, pah1, pah2, pah3, vb0, vb1);
                mma_bf16(o0, pah0, pah1, pah2, pah3, wa0, wa1);
                mma_bf16(o1, pah0, pah1, pah2, pah3, wb0, wb1);
                mma_bf16(o0, pal0, pal1, pal2, pal3, va0, va1);
                mma_bf16(o1, pal0, pal1, pal2, pal3, vb0, vb1);
            }
        }
    }

    // ---- reduce row sums ----
    lsum0 += __shfl_xor_sync(0xffffffffu, lsum0, 1);
    lsum0 += __shfl_xor_sync(0xffffffffu, lsum0, 2);
    lsum1 += __shfl_xor_sync(0xffffffffu, lsum1, 1);
    lsum1 += __shfl_xor_sync(0xffffffffu, lsum1, 2);
    if (c4 == 0) {
        LS[wh][wm + g]     = lsum0;
        LS[wh][wm + g + 8] = lsum1;
    }
    __syncthreads();
    const float inv0 = 1.0f / (LS[0][wm + g] + LS[1][wm + g]);
    const float inv1 = 1.0f / (LS[0][wm + g + 8] + LS[1][wm + g + 8]);

    // ---- store O ----
    {
        float* r0p = ao + (size_t)(q0 + wm + g) * (NH * HD) + h * HD + wh * 128;
        float* r1p = ao + (size_t)(q0 + wm + g + 8) * (NH * HD) + h * HD + wh * 128;
#pragma unroll
        for (int nf = 0; nf < 16; nf++) {
            const int dc = nf * 8 + 2 * c4;
            *(float2*)(r0p + dc) = make_float2(oacc[nf][0] * inv0, oacc[nf][1] * inv0);
            *(float2*)(r1p + dc) = make_float2(oacc[nf][2] * inv1, oacc[nf][3] * inv1);
        }
    }
}

// ---------------------------------------------------------------------------
// Inputs: hidden f32 [1,4096,2304], mask (ignored — analytic), Wq [2048,2304],
// Wk [1024,2304], Wv [1024,2304], Wo [2304,2048], position_ids i32 [1,4096].
// ---------------------------------------------------------------------------
extern "C" void kernel_launch(void* const* d_in, const int* in_sizes, int n_in,
                              void* d_out, int out_size)
{
    const float* hidden = (const float*)d_in[0];
    const float* Wq     = (const float*)d_in[2];
    const float* Wk     = (const float*)d_in[3];
    const float* Wv     = (const float*)d_in[4];
    const float* Wo     = (const float*)d_in[5];
    const int*   pos    = (const int*)d_in[6];
    float*       out    = (float*)d_out;

    float *qkv, *ao;
    cudaGetSymbolAddress((void**)&qkv, g_qkv);
    cudaGetSymbolAddress((void**)&ao,  g_ao);

    cudaFuncSetAttribute(attn_mma7, cudaFuncAttributeMaxDynamicSharedMemorySize, ATTN_SMEM_BYTES);

    // QKV projections (proven)
    gemm_bf16s<<<dim3(16, 32), 256>>>(hidden, Wq, qkv, HIDDEN, HIDDEN, HIDDEN, QKVN, 0);
    gemm_bf16s<<<dim3(8, 32), 256>>>(hidden, Wk, qkv, HIDDEN, HIDDEN, HIDDEN, QKVN, 2048);
    gemm_bf16s<<<dim3(8, 32), 256>>>(hidden, Wv, qkv, HIDDEN, HIDDEN, HIDDEN, QKVN, 3072);

    // RoPE (proven)
    rope_kernel<<<S_LEN, 128>>>(qkv, pos);

    // One-time K/V hi/lo split into copy-ready layouts
    prep_split<<<dim3(S_LEN / 32, NKV), 256>>>(qkv);

    // Tensor-core attention: reversed work order + pair barriers
    attn_mma7<<<dim3(S_LEN / 64, NH), 256, ATTN_SMEM_BYTES>>>(qkv, ao);

    // Output projection (proven)
    gemm_bf16s<<<dim3(18, 32), 256>>>(ao, Wo, out, NH * HD, NH * HD, NH * HD, HIDDEN, 0);
}